// round 14
// baseline (speedup 1.0000x reference)
#include <cuda_runtime.h>
#include <cuda_fp16.h>
#include <cstdint>
#include <math.h>

// ---------------- problem constants ----------------
#define S_LEN   2048
#define D_DIM   2048
#define H_N     16
#define NOPE_D  128
#define ROPE_D  64
#define QK_D    192
#define VH_D    128
#define QLORA   1536
#define KVLORA  512
#define KVD     576
#define QUP_N   (H_N*QK_D)            // 3072
#define KVUP_N  (H_N*(NOPE_D+VH_D))   // 4096
#define ATTN_N  (H_N*VH_D)            // 2048

typedef __half fp16;

// ---------------- scratch ----------------
__device__ float g_qdown[S_LEN*QLORA];
__device__ float g_kv   [S_LEN*KVD];

// activations: fp16 hi only
__device__ fp16 g_xh[S_LEN*D_DIM];
__device__ fp16 g_qdnh[S_LEN*QLORA];
__device__ fp16 g_kvnh[S_LEN*KVLORA];
__device__ fp16 g_attnh[S_LEN*ATTN_N];
__device__ fp16 g_qfh[S_LEN*QUP_N];
// K/V (B-side of flash): hi + lo
__device__ fp16 g_kfh[S_LEN*QUP_N],  g_kfl[S_LEN*QUP_N];
__device__ fp16 g_vfh[S_LEN*ATTN_N], g_vfl[S_LEN*ATTN_N];
// weights: hi + lo
__device__ fp16 g_wqdh[QLORA*D_DIM],    g_wqdl[QLORA*D_DIM];
__device__ fp16 g_wkvdh[KVD*D_DIM],     g_wkvdl[KVD*D_DIM];
__device__ fp16 g_wquh[QUP_N*QLORA],    g_wqul[QUP_N*QLORA];
__device__ fp16 g_wkvuh[KVUP_N*KVLORA], g_wkvul[KVUP_N*KVLORA];
__device__ fp16 g_woh[D_DIM*ATTN_N],    g_wol[D_DIM*ATTN_N];

// flash split-KV scratch
__device__ float g_fo[16*8*2*128*128];
__device__ float g_fm[16*8*2*128];
__device__ float g_fl[16*8*2*128];

// flash CTA schedule: descending work size
__device__ const int c_qb[24] = {15,15,7,14,14,13,13,6,12,12,11,11,5,10,10,9,9,4,8,8,3,2,1,0};
__device__ const int c_pt[24] = {0,1,-1,0,1,0,1,-1,0,1,0,1,-1,0,1,0,1,-1,0,1,-1,-1,-1,-1};

// ---------------- PTX helpers (sm_80+ PTX only; compute_103-safe) ----------------
__device__ __forceinline__ uint32_t smem_u32(const void* p) {
    uint32_t a;
    asm("{ .reg .u64 t; cvta.to.shared.u64 t, %1; cvt.u32.u64 %0, t; }" : "=r"(a) : "l"(p));
    return a;
}

#define CP_ASYNC16(dst, src, sz) \
    asm volatile("cp.async.cg.shared.global [%0], [%1], 16, %2;" \
        :: "r"(dst), "l"(src), "r"(sz) : "memory")
#define CP_COMMIT()  asm volatile("cp.async.commit_group;" ::: "memory")
#define CP_WAIT(n)   asm volatile("cp.async.wait_group %0;" :: "n"(n) : "memory")

__device__ __forceinline__ void ldsm4(uint32_t addr, uint32_t* f) {
    asm volatile("ldmatrix.sync.aligned.m8n8.x4.shared.b16 {%0,%1,%2,%3}, [%4];"
        : "=r"(f[0]), "=r"(f[1]), "=r"(f[2]), "=r"(f[3]) : "r"(addr));
}
__device__ __forceinline__ void ldsm4t(uint32_t addr, uint32_t* f) {
    asm volatile("ldmatrix.sync.aligned.m8n8.x4.trans.shared.b16 {%0,%1,%2,%3}, [%4];"
        : "=r"(f[0]), "=r"(f[1]), "=r"(f[2]), "=r"(f[3]) : "r"(addr));
}

#define MMAH(d, a, b0, b1) \
    asm volatile("mma.sync.aligned.m16n8k16.row.col.f32.f16.f16.f32 " \
        "{%0,%1,%2,%3}, {%4,%5,%6,%7}, {%8,%9}, {%0,%1,%2,%3};" \
        : "+f"((d)[0]), "+f"((d)[1]), "+f"((d)[2]), "+f"((d)[3]) \
        : "r"((a)[0]), "r"((a)[1]), "r"((a)[2]), "r"((a)[3]), "r"(b0), "r"(b1))

__device__ __forceinline__ uint32_t off16(int r, int c) {
    return (uint32_t)(r * 4 + ((((r >> 1) & 3) ^ c)));
}
__device__ __forceinline__ uint32_t pack_h2(float a, float b) {
    __half2 t = __floats2half2_rn(a, b);
    return *(uint32_t*)&t;
}
__device__ __forceinline__ void split2h(float a, float b, uint32_t& h, uint32_t& l) {
    __half2 hh = __floats2half2_rn(a, b);
    float ar = a - __low2float(hh), br = b - __high2float(hh);
    h = *(uint32_t*)&hh;
    l = pack_h2(ar, br);
}

// ---------------- one-shot convert: x (hi only) + all weights (hi+lo) ----------------
__global__ void __launch_bounds__(256) split_all(
    const float* __restrict__ x,  const float* __restrict__ wqd,
    const float* __restrict__ wkd, const float* __restrict__ wqu,
    const float* __restrict__ wku, const float* __restrict__ wo)
{
    int b = blockIdx.x;
    if (b < 4096) {  // x -> hi only
        int i = b * 256 + threadIdx.x;
        float4 v = ((const float4*)x)[i];
        ((uint2*)g_xh)[i] = make_uint2(pack_h2(v.x, v.y), pack_h2(v.z, v.w));
        return;
    }
    const float* src; fp16 *dh, *dl; int i;
    if (b < 7168)       { src = wqd; dh = g_wqdh;  dl = g_wqdl;  i = (b - 4096) * 256; }
    else if (b < 8320)  { src = wkd; dh = g_wkvdh; dl = g_wkvdl; i = (b - 7168) * 256; }
    else if (b < 12928) { src = wqu; dh = g_wquh;  dl = g_wqul;  i = (b - 8320) * 256; }
    else if (b < 14976) { src = wku; dh = g_wkvuh; dl = g_wkvul; i = (b - 12928) * 256; }
    else                { src = wo;  dh = g_woh;   dl = g_wol;   i = (b - 14976) * 256; }
    i += threadIdx.x;
    float4 v = ((const float4*)src)[i];
    uint32_t h0, l0, h1, l1;
    split2h(v.x, v.y, h0, l0);
    split2h(v.z, v.w, h1, l1);
    ((uint2*)dh)[i] = make_uint2(h0, h1);
    ((uint2*)dl)[i] = make_uint2(l0, l1);
}

// ---------------- fp16 2-pass NT GEMM: 512 threads, 16 warps, warp tile 32x32 ----------------
// 3-stage cp.async pipeline, ONE __syncthreads per k-iteration.
#define GM_SMEM (3*24576)   // 3 stages x (A, Bh, Bl)

__global__ void __launch_bounds__(512, 1) gemm_mma2(
    const fp16* __restrict__ Ah0,
    const fp16* __restrict__ Bh0, const fp16* __restrict__ Bl0,
    const float* __restrict__ bias0, float* __restrict__ C0, int N0, int K0, int mode0, int NX0,
    const fp16* __restrict__ Ah1,
    const fp16* __restrict__ Bh1, const fp16* __restrict__ Bl1,
    const float* __restrict__ bias1, float* __restrict__ C1, int N1, int K1, int mode1,
    const float* __restrict__ fc, const float* __restrict__ fs)
{
    extern __shared__ __align__(1024) char sm[];
    const uint32_t smb = smem_u32(sm);

    const fp16 *Ah, *Bh, *Bl;
    const float* bias;
    float* C;
    int N, K, mode, bx = blockIdx.x;
    if (bx < NX0) {
        Ah = Ah0; Bh = Bh0; Bl = Bl0; bias = bias0; C = C0; N = N0; K = K0; mode = mode0;
    } else {
        bx -= NX0;
        Ah = Ah1; Bh = Bh1; Bl = Bl1; bias = bias1; C = C1; N = N1; K = K1; mode = mode1;
    }

    const int tid = threadIdx.x;
    const int lane = tid & 31;
    const int wid = tid >> 5;          // 0..15
    const int warp_m = wid & 3;
    const int warp_n = wid >> 2;
    const int brow = blockIdx.y * 128;
    const int bcol = bx * 128;

    const int r0g = tid >> 2;
    const int c0g = tid & 3;

    uint32_t aoff[2][2], boff[2][2];
#pragma unroll
    for (int mt = 0; mt < 2; mt++)
#pragma unroll
        for (int ks = 0; ks < 2; ks++) {
            int rr = warp_m * 32 + mt * 16 + (lane & 15);
            int cc = ks * 2 + (lane >> 4);
            aoff[mt][ks] = off16(rr, cc) * 16;
        }
#pragma unroll
    for (int g = 0; g < 2; g++)
#pragma unroll
        for (int ks = 0; ks < 2; ks++) {
            int rr = warp_n * 32 + g * 16 + (lane & 15);
            int cc = ks * 2 + (lane >> 4);
            boff[g][ks] = off16(rr, cc) * 16;
        }

    float acc[2][4][4];
#pragma unroll
    for (int i = 0; i < 2; i++)
#pragma unroll
        for (int j = 0; j < 4; j++)
#pragma unroll
            for (int k = 0; k < 4; k++) acc[i][j][k] = 0.f;

    const int KT = K >> 5;

    auto load_stage = [&](int s, int k0) {
        uint32_t base = smb + s * 24576;
        uint32_t doff = off16(r0g, c0g) * 16;
        size_t ga = (size_t)(brow + r0g) * K + k0 + c0g * 8;
        CP_ASYNC16(base + doff, Ah + ga, 16);
        int gr = bcol + r0g;
        int ok = (gr < N) ? 16 : 0;
        size_t gb = (size_t)(ok ? gr : 0) * K + k0 + c0g * 8;
        CP_ASYNC16(base + 8192 + doff,  Bh + gb, ok);
        CP_ASYNC16(base + 16384 + doff, Bl + gb, ok);
        CP_COMMIT();
    };

    load_stage(0, 0);
    load_stage(1, 32);

    uint32_t af[2][2][4], bfr[2][2][4];

    auto mma_block = [&]() {
#pragma unroll
        for (int mt = 0; mt < 2; mt++)
#pragma unroll
            for (int nt = 0; nt < 4; nt++) {
                int g = nt >> 1, hf = nt & 1;
#pragma unroll
                for (int ks = 0; ks < 2; ks++)
                    MMAH(acc[mt][nt], af[mt][ks],
                         bfr[g][ks][hf], bfr[g][ks][hf + 2]);
            }
    };

    int buf = 0;
    for (int kt = 0; kt < KT; kt++) {
        if (kt + 1 < KT) CP_WAIT(1); else CP_WAIT(0);
        __syncthreads();
        if (kt + 2 < KT) {
            int nb = buf + 2; if (nb >= 3) nb -= 3;
            load_stage(nb, (kt + 2) * 32);
        }

        uint32_t st = smb + buf * 24576;

#pragma unroll
        for (int mt = 0; mt < 2; mt++)
#pragma unroll
            for (int ks = 0; ks < 2; ks++)
                ldsm4(st + aoff[mt][ks], af[mt][ks]);
#pragma unroll
        for (int g = 0; g < 2; g++)
#pragma unroll
            for (int ks = 0; ks < 2; ks++)
                ldsm4(st + 8192 + boff[g][ks], bfr[g][ks]);
        mma_block();

#pragma unroll
        for (int g = 0; g < 2; g++)
#pragma unroll
            for (int ks = 0; ks < 2; ks++)
                ldsm4(st + 16384 + boff[g][ks], bfr[g][ks]);
        mma_block();

        buf++; if (buf >= 3) buf = 0;
    }

    // ---- fused epilogues ----
#pragma unroll
    for (int mt = 0; mt < 2; mt++) {
        int row = brow + warp_m * 32 + mt * 16 + (lane >> 2);
#pragma unroll
        for (int nt = 0; nt < 4; nt++) {
            int col = bcol + warp_n * 32 + nt * 8 + (lane & 3) * 2;
            if (col >= N) continue;
            float b0 = bias[col], b1 = bias[col + 1];
            float v00 = acc[mt][nt][0] + b0, v01 = acc[mt][nt][1] + b1;
            float v10 = acc[mt][nt][2] + b0, v11 = acc[mt][nt][3] + b1;

            if (mode == 0) {
                *(float2*)(C + (size_t)row * N + col) = make_float2(v00, v01);
                *(float2*)(C + (size_t)(row + 8) * N + col) = make_float2(v10, v11);
            } else if (mode == 1) {
                int h = col / QK_D, d = col - h * QK_D;
                if (d >= NOPE_D) {
                    int p0 = (d - NOPE_D) >> 1;
                    float c0 = fc[row * 32 + p0], s0 = fs[row * 32 + p0];
                    float t0 = v00 * c0 - v01 * s0;
                    v01 = v00 * s0 + v01 * c0; v00 = t0;
                    float c1 = fc[(row + 8) * 32 + p0], s1 = fs[(row + 8) * 32 + p0];
                    float t1 = v10 * c1 - v11 * s1;
                    v11 = v10 * s1 + v11 * c1; v10 = t1;
                }
                size_t o0 = ((size_t)row * H_N + h) * QK_D + d;
                size_t o1 = ((size_t)(row + 8) * H_N + h) * QK_D + d;
                *(uint32_t*)(g_qfh + o0) = pack_h2(v00, v01);
                *(uint32_t*)(g_qfh + o1) = pack_h2(v10, v11);
            } else if (mode == 2) {
                int h = col >> 8, dd = col & 255;
                uint32_t hh, ll;
                if (dd < NOPE_D) {
                    size_t o0 = ((size_t)row * H_N + h) * QK_D + dd;
                    size_t o1 = ((size_t)(row + 8) * H_N + h) * QK_D + dd;
                    split2h(v00, v01, hh, ll);
                    *(uint32_t*)(g_kfh + o0) = hh; *(uint32_t*)(g_kfl + o0) = ll;
                    split2h(v10, v11, hh, ll);
                    *(uint32_t*)(g_kfh + o1) = hh; *(uint32_t*)(g_kfl + o1) = ll;
                } else {
                    size_t o0 = ((size_t)row * H_N + h) * VH_D + (dd - NOPE_D);
                    size_t o1 = ((size_t)(row + 8) * H_N + h) * VH_D + (dd - NOPE_D);
                    split2h(v00, v01, hh, ll);
                    *(uint32_t*)(g_vfh + o0) = hh; *(uint32_t*)(g_vfl + o0) = ll;
                    split2h(v10, v11, hh, ll);
                    *(uint32_t*)(g_vfh + o1) = hh; *(uint32_t*)(g_vfl + o1) = ll;
                }
            } else {  // mode 3: kv_down
                *(float2*)(C + (size_t)row * N + col) = make_float2(v00, v01);
                *(float2*)(C + (size_t)(row + 8) * N + col) = make_float2(v10, v11);
                if (col >= KVLORA) {
                    int d = col - KVLORA;
                    int p0 = d >> 1;
                    float c0 = fc[row * 32 + p0], s0 = fs[row * 32 + p0];
                    float r00 = v00 * c0 - v01 * s0;
                    float r01 = v00 * s0 + v01 * c0;
                    float c1 = fc[(row + 8) * 32 + p0], s1 = fs[(row + 8) * 32 + p0];
                    float r10 = v10 * c1 - v11 * s1;
                    float r11 = v10 * s1 + v11 * c1;
                    uint32_t h0p, l0p, h1p, l1p;
                    split2h(r00, r01, h0p, l0p);
                    split2h(r10, r11, h1p, l1p);
#pragma unroll
                    for (int hh = 0; hh < H_N; hh++) {
                        size_t o0 = ((size_t)row * H_N + hh) * QK_D + NOPE_D + d;
                        size_t o1 = ((size_t)(row + 8) * H_N + hh) * QK_D + NOPE_D + d;
                        *(uint32_t*)(g_kfh + o0) = h0p; *(uint32_t*)(g_kfl + o0) = l0p;
                        *(uint32_t*)(g_kfh + o1) = h1p; *(uint32_t*)(g_kfl + o1) = l1p;
                    }
                }
            }
        }
    }
}

// ---------------- fused dual RMSNorm -> fp16 (hi only) ----------------
__global__ void __launch_bounds__(256) mla_rmsnorm2(
    const float* __restrict__ qnw, const float* __restrict__ kvnw)
{
    int row = blockIdx.x;
    const float* x; const float* w; fp16* y; int L;
    if (row < S_LEN) {
        x = g_qdown + (size_t)row * QLORA; w = qnw;
        y = g_qdnh + (size_t)row * QLORA; L = QLORA;
    } else {
        row -= S_LEN;
        x = g_kv + (size_t)row * KVD; w = kvnw;
        y = g_kvnh + (size_t)row * KVLORA; L = KVLORA;
    }
    float ss = 0.f;
    for (int c = threadIdx.x; c < L; c += blockDim.x) {
        float v = x[c];
        ss = fmaf(v, v, ss);
    }
#pragma unroll
    for (int o = 16; o; o >>= 1) ss += __shfl_xor_sync(0xffffffffu, ss, o);
    __shared__ float red[8];
    __shared__ float s_inv;
    if ((threadIdx.x & 31) == 0) red[threadIdx.x >> 5] = ss;
    __syncthreads();
    if (threadIdx.x == 0) {
        float t = 0.f;
#pragma unroll
        for (int i = 0; i < 8; i++) t += red[i];
        s_inv = rsqrtf(t / (float)L + 1e-6f);
    }
    __syncthreads();
    float inv = s_inv;
    for (int c = threadIdx.x; c < L / 2; c += blockDim.x) {
        float2 v = ((const float2*)x)[c];
        float2 ww = ((const float2*)w)[c];
        *(uint32_t*)(y + c * 2) = pack_h2(ww.x * (v.x * inv), ww.y * (v.y * inv));
    }
}

// ---------------- fp16 flash attention (causal, split-KV, 2-pass) ----------------
// 3-stage K/V pipeline, ONE __syncthreads per key-block iteration.
#define FQ 128
#define FK 32
#define QSTRB 400
#define VSTRB 272
#define SQ  0
#define SK  51200            // 3 stages x (Kh 12800 + Kl 12800)
#define KSTAGE 25600
#define SV  128000           // 3 stages x (Vh 8704 + Vl 8704)
#define VSTAGE 17408
#define FLASH_SMEM 180224

__global__ void __launch_bounds__(256, 1) mla_flash_mma(
    const fp16* __restrict__ Qh,
    const fp16* __restrict__ Kh, const fp16* __restrict__ Kl,
    const fp16* __restrict__ Vh, const fp16* __restrict__ Vl,
    fp16* __restrict__ O)
{
    extern __shared__ __align__(1024) char fsmem[];
    const uint32_t smb = smem_u32(fsmem);

    const int h = blockIdx.y;
    const int qb = c_qb[blockIdx.x];
    const int part = c_pt[blockIdx.x];
    const int qbase = qb * FQ;
    const int tid = threadIdx.x;
    const int lane = tid & 31;
    const int wid = tid >> 5;
    const int row_min = qbase + wid * 16;

    const int u_total = 4 * (qb + 1);
    const int u_cnt = (part < 0) ? u_total : (u_total >> 1);
    const int u0 = (part < 0) ? 0 : part * u_cnt;

    for (int i = tid; i < FQ * 24; i += 256) {
        int r = i / 24, c = i % 24;
        size_t go = ((size_t)(qbase + r) * H_N + h) * QK_D + c * 8;
        CP_ASYNC16(smb + SQ + (uint32_t)(r * QSTRB + c * 16), Qh + go, 16);
    }
    CP_COMMIT();

    auto load_kv = [&](int s, int kbase) {
        uint32_t kbp = smb + SK + s * KSTAGE;
        uint32_t vbp = smb + SV + s * VSTAGE;
#pragma unroll
        for (int it = 0; it < 3; it++) {
            int i = tid + it * 256;
            int r = i / 24, c = i % 24;
            size_t go = ((size_t)(kbase + r) * H_N + h) * QK_D + c * 8;
            uint32_t so = (uint32_t)(r * QSTRB + c * 16);
            CP_ASYNC16(kbp + so, Kh + go, 16);
            CP_ASYNC16(kbp + 12800 + so, Kl + go, 16);
        }
#pragma unroll
        for (int it = 0; it < 2; it++) {
            int i = tid + it * 256;
            int r = i >> 4, c = i & 15;
            size_t go = ((size_t)(kbase + r) * H_N + h) * VH_D + c * 8;
            uint32_t so = (uint32_t)(r * VSTRB + c * 16);
            CP_ASYNC16(vbp + so, Vh + go, 16);
            CP_ASYNC16(vbp + 8704 + so, Vl + go, 16);
        }
        CP_COMMIT();
    };

    const uint32_t qfb = smb + SQ + (uint32_t)((wid * 16 + (lane & 15)) * QSTRB + (lane >> 4) * 16);
    const uint32_t kfrel = (uint32_t)((lane & 15) * QSTRB + (lane >> 4) * 16);
    const uint32_t vfrel = (uint32_t)((lane & 15) * VSTRB + (lane >> 4) * 16);

    float o[16][4];
#pragma unroll
    for (int g = 0; g < 16; g++)
#pragma unroll
        for (int j = 0; j < 4; j++) o[g][j] = 0.f;
    float m0 = -1e30f, m1 = -1e30f, l0 = 0.f, l1 = 0.f;
    const float scale = 0.07216878364870322f;

    // prime 2 stages
    load_kv(0, u0 * FK);
    if (u_cnt > 1) load_kv(1, (u0 + 1) * FK);

    int buf = 0;
    for (int kb = 0; kb < u_cnt; kb++) {
        const int kbase = (u0 + kb) * FK;
        if (kb + 1 < u_cnt) CP_WAIT(1); else CP_WAIT(0);
        __syncthreads();                       // single barrier per iteration
        if (kb + 2 < u_cnt) {
            int nb = buf + 2; if (nb >= 3) nb -= 3;
            load_kv(nb, (u0 + kb + 2) * FK);
        }

        if (kbase <= row_min) {
            uint32_t kst = smb + SK + buf * KSTAGE;
            uint32_t vst = smb + SV + buf * VSTAGE;

            float c[4][4];
#pragma unroll
            for (int g = 0; g < 4; g++)
#pragma unroll
                for (int j = 0; j < 4; j++) c[g][j] = 0.f;

#pragma unroll
            for (int ks = 0; ks < 12; ks++) {
                uint32_t ah[4];
                ldsm4(qfb + ks * 32, ah);
#pragma unroll
                for (int gg = 0; gg < 2; gg++) {
                    uint32_t bh[4], bl[4];
                    ldsm4(kst + kfrel + gg * (16 * QSTRB) + ks * 32, bh);
                    ldsm4(kst + 12800 + kfrel + gg * (16 * QSTRB) + ks * 32, bl);
                    MMAH(c[2 * gg],     ah, bh[0], bh[2]);
                    MMAH(c[2 * gg + 1], ah, bh[1], bh[3]);
                    MMAH(c[2 * gg],     ah, bl[0], bl[2]);
                    MMAH(c[2 * gg + 1], ah, bl[1], bl[3]);
                }
            }

            const int row0 = row_min + (lane >> 2);
            const bool needmask = (kbase + FK - 1 > row_min);
#pragma unroll
            for (int g = 0; g < 4; g++) {
                int col = kbase + g * 8 + (lane & 3) * 2;
#pragma unroll
                for (int j = 0; j < 4; j++) {
                    float v = c[g][j] * scale;
                    if (needmask) {
                        int cc = col + (j & 1);
                        int rr = row0 + ((j >> 1) << 3);
                        if (cc > rr) v = -1e30f;
                    }
                    c[g][j] = v;
                }
            }

            float mx0 = -1e30f, mx1 = -1e30f;
#pragma unroll
            for (int g = 0; g < 4; g++) {
                mx0 = fmaxf(mx0, fmaxf(c[g][0], c[g][1]));
                mx1 = fmaxf(mx1, fmaxf(c[g][2], c[g][3]));
            }
#pragma unroll
            for (int off = 1; off < 4; off <<= 1) {
                mx0 = fmaxf(mx0, __shfl_xor_sync(0xffffffffu, mx0, off));
                mx1 = fmaxf(mx1, __shfl_xor_sync(0xffffffffu, mx1, off));
            }
            float mn0 = fmaxf(m0, mx0), mn1 = fmaxf(m1, mx1);
            float al0 = __expf(m0 - mn0), al1 = __expf(m1 - mn1);
            float rs0 = 0.f, rs1 = 0.f;
#pragma unroll
            for (int g = 0; g < 4; g++) {
                c[g][0] = __expf(c[g][0] - mn0); rs0 += c[g][0];
                c[g][1] = __expf(c[g][1] - mn0); rs0 += c[g][1];
                c[g][2] = __expf(c[g][2] - mn1); rs1 += c[g][2];
                c[g][3] = __expf(c[g][3] - mn1); rs1 += c[g][3];
            }
#pragma unroll
            for (int off = 1; off < 4; off <<= 1) {
                rs0 += __shfl_xor_sync(0xffffffffu, rs0, off);
                rs1 += __shfl_xor_sync(0xffffffffu, rs1, off);
            }
            l0 = l0 * al0 + rs0; l1 = l1 * al1 + rs1;
            m0 = mn0; m1 = mn1;
#pragma unroll
            for (int g = 0; g < 16; g++) {
                o[g][0] *= al0; o[g][1] *= al0;
                o[g][2] *= al1; o[g][3] *= al1;
            }

#pragma unroll
            for (int kc = 0; kc < 2; kc++) {
                uint32_t aph[4];
                aph[0] = pack_h2(c[2 * kc][0],     c[2 * kc][1]);
                aph[1] = pack_h2(c[2 * kc][2],     c[2 * kc][3]);
                aph[2] = pack_h2(c[2 * kc + 1][0], c[2 * kc + 1][1]);
                aph[3] = pack_h2(c[2 * kc + 1][2], c[2 * kc + 1][3]);
#pragma unroll
                for (int ng = 0; ng < 8; ng++) {
                    uint32_t vh4[4], vl4[4];
                    ldsm4t(vst + vfrel + kc * (16 * VSTRB) + ng * 32, vh4);
                    ldsm4t(vst + 8704 + vfrel + kc * (16 * VSTRB) + ng * 32, vl4);
                    MMAH(o[2 * ng],     aph, vh4[0], vh4[1]);
                    MMAH(o[2 * ng + 1], aph, vh4[2], vh4[3]);
                    MMAH(o[2 * ng],     aph, vl4[0], vl4[1]);
                    MMAH(o[2 * ng + 1], aph, vl4[2], vl4[3]);
                }
            }
        }
        buf++; if (buf >= 3) buf = 0;
    }

    const int rl0 = wid * 16 + (lane >> 2);
    if (part < 0) {
        float inv0 = 1.0f / l0, inv1 = 1.0f / l1;
        int row0 = qbase + rl0;
#pragma unroll
        for (int g = 0; g < 16; g++) {
            int col = h * VH_D + g * 8 + (lane & 3) * 2;
            *(uint32_t*)(O + (size_t)row0 * ATTN_N + col) =
                pack_h2(o[g][0] * inv0, o[g][1] * inv0);
            *(uint32_t*)(O + (size_t)(row0 + 8) * ATTN_N + col) =
                pack_h2(o[g][2] * inv1, o[g][3] * inv1);
        }
    } else {
        const int sb = (h * 8 + (qb - 8)) * 2 + part;
        const size_t ob0 = ((size_t)sb * 128 + rl0) * 128;
        const size_t ob1 = ((size_t)sb * 128 + rl0 + 8) * 128;
#pragma unroll
        for (int g = 0; g < 16; g++) {
            int col = g * 8 + (lane & 3) * 2;
            *(float2*)(g_fo + ob0 + col) = make_float2(o[g][0], o[g][1]);
            *(float2*)(g_fo + ob1 + col) = make_float2(o[g][2], o[g][3]);
        }
        if ((lane & 3) == 0) {
            g_fm[sb * 128 + rl0] = m0;     g_fl[sb * 128 + rl0] = l0;
            g_fm[sb * 128 + rl0 + 8] = m1; g_fl[sb * 128 + rl0 + 8] = l1;
        }
    }
}

// ---------------- flash split-KV merge ----------------
__global__ void __launch_bounds__(256) flash_merge(fp16* __restrict__ O)
{
    int t = threadIdx.x;
    int rl = blockIdx.x * 4 + (t >> 6);
    int h = rl >> 10;
    int rem = rl & 1023;
    int qbs = rem >> 7;
    int row = rem & 127;
    int c = (t & 63) * 2;

    int i0 = ((h * 8 + qbs) * 2 + 0) * 128 + row;
    int i1 = ((h * 8 + qbs) * 2 + 1) * 128 + row;
    float m0 = g_fm[i0], m1 = g_fm[i1];
    float l0 = g_fl[i0], l1 = g_fl[i1];
    float m = fmaxf(m0, m1);
    float w0 = __expf(m0 - m), w1 = __expf(m1 - m);
    float inv = 1.f / (w0 * l0 + w1 * l1);

    float2 a = *(float2*)(g_fo + (size_t)i0 * 128 + c);
    float2 b = *(float2*)(g_fo + (size_t)i1 * 128 + c);
    size_t off = (size_t)((qbs + 8) * 128 + row) * ATTN_N + h * VH_D + c;
    *(uint32_t*)(O + off) = pack_h2((w0 * a.x + w1 * b.x) * inv,
                                    (w0 * a.y + w1 * b.y) * inv);
}

// ---------------- launch ----------------
extern "C" void kernel_launch(void* const* d_in, const int* in_sizes, int n_in,
                              void* d_out, int out_size)
{
    const float* x          = (const float*)d_in[0];
    const float* fcos       = (const float*)d_in[2];
    const float* fsin       = (const float*)d_in[3];
    const float* wq_down_w  = (const float*)d_in[5];
    const float* wq_down_b  = (const float*)d_in[6];
    const float* q_norm_w   = (const float*)d_in[7];
    const float* wq_up_w    = (const float*)d_in[8];
    const float* wq_up_b    = (const float*)d_in[9];
    const float* wkv_down_w = (const float*)d_in[10];
    const float* wkv_down_b = (const float*)d_in[11];
    const float* kv_norm_w  = (const float*)d_in[12];
    const float* wkv_up_w   = (const float*)d_in[13];
    const float* wkv_up_b   = (const float*)d_in[14];
    const float* wo_w       = (const float*)d_in[15];
    const float* wo_b       = (const float*)d_in[16];
    float* out = (float*)d_out;

    float *qdown, *kv;
    fp16 *xh, *qdnh, *kvnh, *attnh, *qfh, *kfh, *kfl, *vfh, *vfl;
    fp16 *wqdh, *wqdl, *wkvdh, *wkvdl, *wquh, *wqul, *wkvuh, *wkvul, *woh, *wol;
    cudaGetSymbolAddress((void**)&qdown, g_qdown);
    cudaGetSymbolAddress((void**)&kv,    g_kv);
    cudaGetSymbolAddress((void**)&xh, g_xh);
    cudaGetSymbolAddress((void**)&qdnh, g_qdnh);
    cudaGetSymbolAddress((void**)&kvnh, g_kvnh);
    cudaGetSymbolAddress((void**)&attnh, g_attnh);
    cudaGetSymbolAddress((void**)&qfh, g_qfh);
    cudaGetSymbolAddress((void**)&kfh, g_kfh);     cudaGetSymbolAddress((void**)&kfl, g_kfl);
    cudaGetSymbolAddress((void**)&vfh, g_vfh);     cudaGetSymbolAddress((void**)&vfl, g_vfl);
    cudaGetSymbolAddress((void**)&wqdh, g_wqdh);   cudaGetSymbolAddress((void**)&wqdl, g_wqdl);
    cudaGetSymbolAddress((void**)&wkvdh, g_wkvdh); cudaGetSymbolAddress((void**)&wkvdl, g_wkvdl);
    cudaGetSymbolAddress((void**)&wquh, g_wquh);   cudaGetSymbolAddress((void**)&wqul, g_wqul);
    cudaGetSymbolAddress((void**)&wkvuh, g_wkvuh); cudaGetSymbolAddress((void**)&wkvul, g_wkvul);
    cudaGetSymbolAddress((void**)&woh, g_woh);     cudaGetSymbolAddress((void**)&wol, g_wol);

    cudaFuncSetAttribute(gemm_mma2, cudaFuncAttributeMaxDynamicSharedMemorySize, GM_SMEM);
    cudaFuncSetAttribute(mla_flash_mma, cudaFuncAttributeMaxDynamicSharedMemorySize, FLASH_SMEM);

    // one-shot convert: x (hi) + all 5 weights (hi+lo)
    split_all<<<19072, 256>>>(x, wq_down_w, wkv_down_w, wq_up_w, wkv_up_w, wo_w);

    // batched down projections: q_down (mode 0) + kv_down (mode 3)
    gemm_mma2<<<dim3(12 + 5, S_LEN / 128), 512, GM_SMEM>>>(
        xh, wqdh, wqdl, wq_down_b, qdown, QLORA, D_DIM, 0, 12,
        xh, wkvdh, wkvdl, wkv_down_b, kv, KVD, D_DIM, 3,
        fcos, fsin);

    // fused dual rmsnorm
    mla_rmsnorm2<<<2 * S_LEN, 256>>>(q_norm_w, kv_norm_w);

    // batched up projections: q_up (mode 1) + kv_up (mode 2)
    gemm_mma2<<<dim3(24 + 32, S_LEN / 128), 512, GM_SMEM>>>(
        qdnh, wquh, wqul, wq_up_b, qdown, QUP_N, QLORA, 1, 24,
        kvnh, wkvuh, wkvul, wkv_up_b, qdown, KVUP_N, KVLORA, 2,
        fcos, fsin);

    // flash attention with split-KV (384 CTAs, size-descending, 3-stage pipeline)
    mla_flash_mma<<<dim3(24, H_N), 256, FLASH_SMEM>>>(
        qfh, kfh, kfl, vfh, vfl, attnh);
    flash_merge<<<4096, 256>>>(attnh);

    // output projection (mode 0; second slot inert)
    gemm_mma2<<<dim3(16, S_LEN / 128), 512, GM_SMEM>>>(
        attnh, woh, wol, wo_b, out, D_DIM, ATTN_N, 0, 16,
        attnh, woh, wol, wo_b, out, D_DIM, ATTN_N, 0,
        fcos, fsin);
}

// round 15
// speedup vs baseline: 1.0419x; 1.0419x over previous
#include <cuda_runtime.h>
#include <cuda_fp16.h>
#include <cstdint>
#include <math.h>

// ---------------- problem constants ----------------
#define S_LEN   2048
#define D_DIM   2048
#define H_N     16
#define NOPE_D  128
#define ROPE_D  64
#define QK_D    192
#define VH_D    128
#define QLORA   1536
#define KVLORA  512
#define KVD     576
#define QUP_N   (H_N*QK_D)            // 3072
#define KVUP_N  (H_N*(NOPE_D+VH_D))   // 4096
#define ATTN_N  (H_N*VH_D)            // 2048

typedef __half fp16;

// ---------------- scratch ----------------
__device__ float g_qdown[S_LEN*QLORA];
__device__ float g_kv   [S_LEN*KVD];

// activations: fp16 hi only
__device__ fp16 g_xh[S_LEN*D_DIM];
__device__ fp16 g_qdnh[S_LEN*QLORA];
__device__ fp16 g_kvnh[S_LEN*KVLORA];
__device__ fp16 g_attnh[S_LEN*ATTN_N];
__device__ fp16 g_qfh[S_LEN*QUP_N];
// K (B-side of QK): hi + lo;  V: hi only (lo dropped; +~2.4e-4 rel err)
__device__ fp16 g_kfh[S_LEN*QUP_N],  g_kfl[S_LEN*QUP_N];
__device__ fp16 g_vfh[S_LEN*ATTN_N];
// weights: hi + lo
__device__ fp16 g_wqdh[QLORA*D_DIM],    g_wqdl[QLORA*D_DIM];
__device__ fp16 g_wkvdh[KVD*D_DIM],     g_wkvdl[KVD*D_DIM];
__device__ fp16 g_wquh[QUP_N*QLORA],    g_wqul[QUP_N*QLORA];
__device__ fp16 g_wkvuh[KVUP_N*KVLORA], g_wkvul[KVUP_N*KVLORA];
__device__ fp16 g_woh[D_DIM*ATTN_N],    g_wol[D_DIM*ATTN_N];

// flash split-KV scratch
__device__ float g_fo[16*8*2*128*128];
__device__ float g_fm[16*8*2*128];
__device__ float g_fl[16*8*2*128];

// flash CTA schedule: descending work size
__device__ const int c_qb[24] = {15,15,7,14,14,13,13,6,12,12,11,11,5,10,10,9,9,4,8,8,3,2,1,0};
__device__ const int c_pt[24] = {0,1,-1,0,1,0,1,-1,0,1,0,1,-1,0,1,0,1,-1,0,1,-1,-1,-1,-1};

// ---------------- PTX helpers (sm_80+ PTX only; compute_103-safe) ----------------
__device__ __forceinline__ uint32_t smem_u32(const void* p) {
    uint32_t a;
    asm("{ .reg .u64 t; cvta.to.shared.u64 t, %1; cvt.u32.u64 %0, t; }" : "=r"(a) : "l"(p));
    return a;
}

#define CP_ASYNC16(dst, src, sz) \
    asm volatile("cp.async.cg.shared.global [%0], [%1], 16, %2;" \
        :: "r"(dst), "l"(src), "r"(sz) : "memory")
#define CP_COMMIT()  asm volatile("cp.async.commit_group;" ::: "memory")
#define CP_WAIT(n)   asm volatile("cp.async.wait_group %0;" :: "n"(n) : "memory")

__device__ __forceinline__ void ldsm4(uint32_t addr, uint32_t* f) {
    asm volatile("ldmatrix.sync.aligned.m8n8.x4.shared.b16 {%0,%1,%2,%3}, [%4];"
        : "=r"(f[0]), "=r"(f[1]), "=r"(f[2]), "=r"(f[3]) : "r"(addr));
}
__device__ __forceinline__ void ldsm4t(uint32_t addr, uint32_t* f) {
    asm volatile("ldmatrix.sync.aligned.m8n8.x4.trans.shared.b16 {%0,%1,%2,%3}, [%4];"
        : "=r"(f[0]), "=r"(f[1]), "=r"(f[2]), "=r"(f[3]) : "r"(addr));
}

#define MMAH(d, a, b0, b1) \
    asm volatile("mma.sync.aligned.m16n8k16.row.col.f32.f16.f16.f32 " \
        "{%0,%1,%2,%3}, {%4,%5,%6,%7}, {%8,%9}, {%0,%1,%2,%3};" \
        : "+f"((d)[0]), "+f"((d)[1]), "+f"((d)[2]), "+f"((d)[3]) \
        : "r"((a)[0]), "r"((a)[1]), "r"((a)[2]), "r"((a)[3]), "r"(b0), "r"(b1))

__device__ __forceinline__ uint32_t off16(int r, int c) {
    return (uint32_t)(r * 4 + ((((r >> 1) & 3) ^ c)));
}
__device__ __forceinline__ uint32_t pack_h2(float a, float b) {
    __half2 t = __floats2half2_rn(a, b);
    return *(uint32_t*)&t;
}
__device__ __forceinline__ void split2h(float a, float b, uint32_t& h, uint32_t& l) {
    __half2 hh = __floats2half2_rn(a, b);
    float ar = a - __low2float(hh), br = b - __high2float(hh);
    h = *(uint32_t*)&hh;
    l = pack_h2(ar, br);
}

// ---------------- one-shot convert: x (hi only) + all weights (hi+lo) ----------------
__global__ void __launch_bounds__(256) split_all(
    const float* __restrict__ x,  const float* __restrict__ wqd,
    const float* __restrict__ wkd, const float* __restrict__ wqu,
    const float* __restrict__ wku, const float* __restrict__ wo)
{
    int b = blockIdx.x;
    if (b < 4096) {  // x -> hi only
        int i = b * 256 + threadIdx.x;
        float4 v = ((const float4*)x)[i];
        ((uint2*)g_xh)[i] = make_uint2(pack_h2(v.x, v.y), pack_h2(v.z, v.w));
        return;
    }
    const float* src; fp16 *dh, *dl; int i;
    if (b < 7168)       { src = wqd; dh = g_wqdh;  dl = g_wqdl;  i = (b - 4096) * 256; }
    else if (b < 8320)  { src = wkd; dh = g_wkvdh; dl = g_wkvdl; i = (b - 7168) * 256; }
    else if (b < 12928) { src = wqu; dh = g_wquh;  dl = g_wqul;  i = (b - 8320) * 256; }
    else if (b < 14976) { src = wku; dh = g_wkvuh; dl = g_wkvul; i = (b - 12928) * 256; }
    else                { src = wo;  dh = g_woh;   dl = g_wol;   i = (b - 14976) * 256; }
    i += threadIdx.x;
    float4 v = ((const float4*)src)[i];
    uint32_t h0, l0, h1, l1;
    split2h(v.x, v.y, h0, l0);
    split2h(v.z, v.w, h1, l1);
    ((uint2*)dh)[i] = make_uint2(h0, h1);
    ((uint2*)dl)[i] = make_uint2(l0, l1);
}

// ---------------- fp16 2-pass NT GEMM: 512 threads, 16 warps, warp tile 32x32 ----------------
// 3-stage cp.async pipeline, ONE __syncthreads per k-iteration.
#define GM_SMEM (3*24576)   // 3 stages x (A, Bh, Bl)

__global__ void __launch_bounds__(512, 1) gemm_mma2(
    const fp16* __restrict__ Ah0,
    const fp16* __restrict__ Bh0, const fp16* __restrict__ Bl0,
    const float* __restrict__ bias0, float* __restrict__ C0, int N0, int K0, int mode0, int NX0,
    const fp16* __restrict__ Ah1,
    const fp16* __restrict__ Bh1, const fp16* __restrict__ Bl1,
    const float* __restrict__ bias1, float* __restrict__ C1, int N1, int K1, int mode1,
    const float* __restrict__ fc, const float* __restrict__ fs)
{
    extern __shared__ __align__(1024) char sm[];
    const uint32_t smb = smem_u32(sm);

    const fp16 *Ah, *Bh, *Bl;
    const float* bias;
    float* C;
    int N, K, mode, bx = blockIdx.x;
    if (bx < NX0) {
        Ah = Ah0; Bh = Bh0; Bl = Bl0; bias = bias0; C = C0; N = N0; K = K0; mode = mode0;
    } else {
        bx -= NX0;
        Ah = Ah1; Bh = Bh1; Bl = Bl1; bias = bias1; C = C1; N = N1; K = K1; mode = mode1;
    }

    const int tid = threadIdx.x;
    const int lane = tid & 31;
    const int wid = tid >> 5;          // 0..15
    const int warp_m = wid & 3;
    const int warp_n = wid >> 2;
    const int brow = blockIdx.y * 128;
    const int bcol = bx * 128;

    const int r0g = tid >> 2;
    const int c0g = tid & 3;

    uint32_t aoff[2][2], boff[2][2];
#pragma unroll
    for (int mt = 0; mt < 2; mt++)
#pragma unroll
        for (int ks = 0; ks < 2; ks++) {
            int rr = warp_m * 32 + mt * 16 + (lane & 15);
            int cc = ks * 2 + (lane >> 4);
            aoff[mt][ks] = off16(rr, cc) * 16;
        }
#pragma unroll
    for (int g = 0; g < 2; g++)
#pragma unroll
        for (int ks = 0; ks < 2; ks++) {
            int rr = warp_n * 32 + g * 16 + (lane & 15);
            int cc = ks * 2 + (lane >> 4);
            boff[g][ks] = off16(rr, cc) * 16;
        }

    float acc[2][4][4];
#pragma unroll
    for (int i = 0; i < 2; i++)
#pragma unroll
        for (int j = 0; j < 4; j++)
#pragma unroll
            for (int k = 0; k < 4; k++) acc[i][j][k] = 0.f;

    const int KT = K >> 5;

    auto load_stage = [&](int s, int k0) {
        uint32_t base = smb + s * 24576;
        uint32_t doff = off16(r0g, c0g) * 16;
        size_t ga = (size_t)(brow + r0g) * K + k0 + c0g * 8;
        CP_ASYNC16(base + doff, Ah + ga, 16);
        int gr = bcol + r0g;
        int ok = (gr < N) ? 16 : 0;
        size_t gb = (size_t)(ok ? gr : 0) * K + k0 + c0g * 8;
        CP_ASYNC16(base + 8192 + doff,  Bh + gb, ok);
        CP_ASYNC16(base + 16384 + doff, Bl + gb, ok);
        CP_COMMIT();
    };

    load_stage(0, 0);
    load_stage(1, 32);

    uint32_t af[2][2][4], bfr[2][2][4];

    auto mma_block = [&]() {
#pragma unroll
        for (int mt = 0; mt < 2; mt++)
#pragma unroll
            for (int nt = 0; nt < 4; nt++) {
                int g = nt >> 1, hf = nt & 1;
#pragma unroll
                for (int ks = 0; ks < 2; ks++)
                    MMAH(acc[mt][nt], af[mt][ks],
                         bfr[g][ks][hf], bfr[g][ks][hf + 2]);
            }
    };

    int buf = 0;
    for (int kt = 0; kt < KT; kt++) {
        if (kt + 1 < KT) CP_WAIT(1); else CP_WAIT(0);
        __syncthreads();
        if (kt + 2 < KT) {
            int nb = buf + 2; if (nb >= 3) nb -= 3;
            load_stage(nb, (kt + 2) * 32);
        }

        uint32_t st = smb + buf * 24576;

#pragma unroll
        for (int mt = 0; mt < 2; mt++)
#pragma unroll
            for (int ks = 0; ks < 2; ks++)
                ldsm4(st + aoff[mt][ks], af[mt][ks]);
#pragma unroll
        for (int g = 0; g < 2; g++)
#pragma unroll
            for (int ks = 0; ks < 2; ks++)
                ldsm4(st + 8192 + boff[g][ks], bfr[g][ks]);
        mma_block();

#pragma unroll
        for (int g = 0; g < 2; g++)
#pragma unroll
            for (int ks = 0; ks < 2; ks++)
                ldsm4(st + 16384 + boff[g][ks], bfr[g][ks]);
        mma_block();

        buf++; if (buf >= 3) buf = 0;
    }

    // ---- fused epilogues ----
#pragma unroll
    for (int mt = 0; mt < 2; mt++) {
        int row = brow + warp_m * 32 + mt * 16 + (lane >> 2);
#pragma unroll
        for (int nt = 0; nt < 4; nt++) {
            int col = bcol + warp_n * 32 + nt * 8 + (lane & 3) * 2;
            if (col >= N) continue;
            float b0 = bias[col], b1 = bias[col + 1];
            float v00 = acc[mt][nt][0] + b0, v01 = acc[mt][nt][1] + b1;
            float v10 = acc[mt][nt][2] + b0, v11 = acc[mt][nt][3] + b1;

            if (mode == 0) {
                *(float2*)(C + (size_t)row * N + col) = make_float2(v00, v01);
                *(float2*)(C + (size_t)(row + 8) * N + col) = make_float2(v10, v11);
            } else if (mode == 1) {
                int h = col / QK_D, d = col - h * QK_D;
                if (d >= NOPE_D) {
                    int p0 = (d - NOPE_D) >> 1;
                    float c0 = fc[row * 32 + p0], s0 = fs[row * 32 + p0];
                    float t0 = v00 * c0 - v01 * s0;
                    v01 = v00 * s0 + v01 * c0; v00 = t0;
                    float c1 = fc[(row + 8) * 32 + p0], s1 = fs[(row + 8) * 32 + p0];
                    float t1 = v10 * c1 - v11 * s1;
                    v11 = v10 * s1 + v11 * c1; v10 = t1;
                }
                size_t o0 = ((size_t)row * H_N + h) * QK_D + d;
                size_t o1 = ((size_t)(row + 8) * H_N + h) * QK_D + d;
                *(uint32_t*)(g_qfh + o0) = pack_h2(v00, v01);
                *(uint32_t*)(g_qfh + o1) = pack_h2(v10, v11);
            } else if (mode == 2) {
                int h = col >> 8, dd = col & 255;
                if (dd < NOPE_D) {
                    uint32_t hh, ll;
                    size_t o0 = ((size_t)row * H_N + h) * QK_D + dd;
                    size_t o1 = ((size_t)(row + 8) * H_N + h) * QK_D + dd;
                    split2h(v00, v01, hh, ll);
                    *(uint32_t*)(g_kfh + o0) = hh; *(uint32_t*)(g_kfl + o0) = ll;
                    split2h(v10, v11, hh, ll);
                    *(uint32_t*)(g_kfh + o1) = hh; *(uint32_t*)(g_kfl + o1) = ll;
                } else {
                    size_t o0 = ((size_t)row * H_N + h) * VH_D + (dd - NOPE_D);
                    size_t o1 = ((size_t)(row + 8) * H_N + h) * VH_D + (dd - NOPE_D);
                    *(uint32_t*)(g_vfh + o0) = pack_h2(v00, v01);
                    *(uint32_t*)(g_vfh + o1) = pack_h2(v10, v11);
                }
            } else {  // mode 3: kv_down
                *(float2*)(C + (size_t)row * N + col) = make_float2(v00, v01);
                *(float2*)(C + (size_t)(row + 8) * N + col) = make_float2(v10, v11);
                if (col >= KVLORA) {
                    int d = col - KVLORA;
                    int p0 = d >> 1;
                    float c0 = fc[row * 32 + p0], s0 = fs[row * 32 + p0];
                    float r00 = v00 * c0 - v01 * s0;
                    float r01 = v00 * s0 + v01 * c0;
                    float c1 = fc[(row + 8) * 32 + p0], s1 = fs[(row + 8) * 32 + p0];
                    float r10 = v10 * c1 - v11 * s1;
                    float r11 = v10 * s1 + v11 * c1;
                    uint32_t h0p, l0p, h1p, l1p;
                    split2h(r00, r01, h0p, l0p);
                    split2h(r10, r11, h1p, l1p);
#pragma unroll
                    for (int hh = 0; hh < H_N; hh++) {
                        size_t o0 = ((size_t)row * H_N + hh) * QK_D + NOPE_D + d;
                        size_t o1 = ((size_t)(row + 8) * H_N + hh) * QK_D + NOPE_D + d;
                        *(uint32_t*)(g_kfh + o0) = h0p; *(uint32_t*)(g_kfl + o0) = l0p;
                        *(uint32_t*)(g_kfh + o1) = h1p; *(uint32_t*)(g_kfl + o1) = l1p;
                    }
                }
            }
        }
    }
}

// ---------------- fused dual RMSNorm -> fp16 (hi only) ----------------
__global__ void __launch_bounds__(256) mla_rmsnorm2(
    const float* __restrict__ qnw, const float* __restrict__ kvnw)
{
    int row = blockIdx.x;
    const float* x; const float* w; fp16* y; int L;
    if (row < S_LEN) {
        x = g_qdown + (size_t)row * QLORA; w = qnw;
        y = g_qdnh + (size_t)row * QLORA; L = QLORA;
    } else {
        row -= S_LEN;
        x = g_kv + (size_t)row * KVD; w = kvnw;
        y = g_kvnh + (size_t)row * KVLORA; L = KVLORA;
    }
    float ss = 0.f;
    for (int c = threadIdx.x; c < L; c += blockDim.x) {
        float v = x[c];
        ss = fmaf(v, v, ss);
    }
#pragma unroll
    for (int o = 16; o; o >>= 1) ss += __shfl_xor_sync(0xffffffffu, ss, o);
    __shared__ float red[8];
    __shared__ float s_inv;
    if ((threadIdx.x & 31) == 0) red[threadIdx.x >> 5] = ss;
    __syncthreads();
    if (threadIdx.x == 0) {
        float t = 0.f;
#pragma unroll
        for (int i = 0; i < 8; i++) t += red[i];
        s_inv = rsqrtf(t / (float)L + 1e-6f);
    }
    __syncthreads();
    float inv = s_inv;
    for (int c = threadIdx.x; c < L / 2; c += blockDim.x) {
        float2 v = ((const float2*)x)[c];
        float2 ww = ((const float2*)w)[c];
        *(uint32_t*)(y + c * 2) = pack_h2(ww.x * (v.x * inv), ww.y * (v.y * inv));
    }
}

// ---------------- fp16 flash attention (causal, split-KV; K hi+lo, V hi only) ----------------
// 3-stage K/V pipeline, one __syncthreads per key-block iteration.
#define FQ 128
#define FK 32
#define QSTRB 400
#define VSTRB 272
#define SQ  0
#define SK  51200            // 3 stages x (Kh 12800 + Kl 12800)
#define KSTAGE 25600
#define SV  128000           // 3 stages x (Vh 8704)
#define VSTAGE 8704
#define FLASH_SMEM 154112

__global__ void __launch_bounds__(256, 1) mla_flash_mma(
    const fp16* __restrict__ Qh,
    const fp16* __restrict__ Kh, const fp16* __restrict__ Kl,
    const fp16* __restrict__ Vh,
    fp16* __restrict__ O)
{
    extern __shared__ __align__(1024) char fsmem[];
    const uint32_t smb = smem_u32(fsmem);

    const int h = blockIdx.y;
    const int qb = c_qb[blockIdx.x];
    const int part = c_pt[blockIdx.x];
    const int qbase = qb * FQ;
    const int tid = threadIdx.x;
    const int lane = tid & 31;
    const int wid = tid >> 5;
    const int row_min = qbase + wid * 16;

    const int u_total = 4 * (qb + 1);
    const int u_cnt = (part < 0) ? u_total : (u_total >> 1);
    const int u0 = (part < 0) ? 0 : part * u_cnt;

    for (int i = tid; i < FQ * 24; i += 256) {
        int r = i / 24, c = i % 24;
        size_t go = ((size_t)(qbase + r) * H_N + h) * QK_D + c * 8;
        CP_ASYNC16(smb + SQ + (uint32_t)(r * QSTRB + c * 16), Qh + go, 16);
    }
    CP_COMMIT();

    auto load_kv = [&](int s, int kbase) {
        uint32_t kbp = smb + SK + s * KSTAGE;
        uint32_t vbp = smb + SV + s * VSTAGE;
#pragma unroll
        for (int it = 0; it < 3; it++) {
            int i = tid + it * 256;
            int r = i / 24, c = i % 24;
            size_t go = ((size_t)(kbase + r) * H_N + h) * QK_D + c * 8;
            uint32_t so = (uint32_t)(r * QSTRB + c * 16);
            CP_ASYNC16(kbp + so, Kh + go, 16);
            CP_ASYNC16(kbp + 12800 + so, Kl + go, 16);
        }
        {
            int i = tid;                      // 512 chunks, 2 per thread
            int r = i >> 4, c = i & 15;
            size_t go = ((size_t)(kbase + r) * H_N + h) * VH_D + c * 8;
            CP_ASYNC16(vbp + (uint32_t)(r * VSTRB + c * 16), Vh + go, 16);
            i = tid + 256;
            r = i >> 4; c = i & 15;
            go = ((size_t)(kbase + r) * H_N + h) * VH_D + c * 8;
            CP_ASYNC16(vbp + (uint32_t)(r * VSTRB + c * 16), Vh + go, 16);
        }
        CP_COMMIT();
    };

    const uint32_t qfb = smb + SQ + (uint32_t)((wid * 16 + (lane & 15)) * QSTRB + (lane >> 4) * 16);
    const uint32_t kfrel = (uint32_t)((lane & 15) * QSTRB + (lane >> 4) * 16);
    const uint32_t vfrel = (uint32_t)((lane & 15) * VSTRB + (lane >> 4) * 16);

    float o[16][4];
#pragma unroll
    for (int g = 0; g < 16; g++)
#pragma unroll
        for (int j = 0; j < 4; j++) o[g][j] = 0.f;
    float m0 = -1e30f, m1 = -1e30f, l0 = 0.f, l1 = 0.f;
    const float scale = 0.07216878364870322f;

    load_kv(0, u0 * FK);
    if (u_cnt > 1) load_kv(1, (u0 + 1) * FK);

    int buf = 0;
    for (int kb = 0; kb < u_cnt; kb++) {
        const int kbase = (u0 + kb) * FK;
        if (kb + 1 < u_cnt) CP_WAIT(1); else CP_WAIT(0);
        __syncthreads();
        if (kb + 2 < u_cnt) {
            int nb = buf + 2; if (nb >= 3) nb -= 3;
            load_kv(nb, (u0 + kb + 2) * FK);
        }

        if (kbase <= row_min) {
            uint32_t kst = smb + SK + buf * KSTAGE;
            uint32_t vst = smb + SV + buf * VSTAGE;

            float c[4][4];
#pragma unroll
            for (int g = 0; g < 4; g++)
#pragma unroll
                for (int j = 0; j < 4; j++) c[g][j] = 0.f;

#pragma unroll
            for (int ks = 0; ks < 12; ks++) {
                uint32_t ah[4];
                ldsm4(qfb + ks * 32, ah);
#pragma unroll
                for (int gg = 0; gg < 2; gg++) {
                    uint32_t bh[4], bl[4];
                    ldsm4(kst + kfrel + gg * (16 * QSTRB) + ks * 32, bh);
                    ldsm4(kst + 12800 + kfrel + gg * (16 * QSTRB) + ks * 32, bl);
                    MMAH(c[2 * gg],     ah, bh[0], bh[2]);
                    MMAH(c[2 * gg + 1], ah, bh[1], bh[3]);
                    MMAH(c[2 * gg],     ah, bl[0], bl[2]);
                    MMAH(c[2 * gg + 1], ah, bl[1], bl[3]);
                }
            }

            const int row0 = row_min + (lane >> 2);
            const bool needmask = (kbase + FK - 1 > row_min);
#pragma unroll
            for (int g = 0; g < 4; g++) {
                int col = kbase + g * 8 + (lane & 3) * 2;
#pragma unroll
                for (int j = 0; j < 4; j++) {
                    float v = c[g][j] * scale;
                    if (needmask) {
                        int cc = col + (j & 1);
                        int rr = row0 + ((j >> 1) << 3);
                        if (cc > rr) v = -1e30f;
                    }
                    c[g][j] = v;
                }
            }

            float mx0 = -1e30f, mx1 = -1e30f;
#pragma unroll
            for (int g = 0; g < 4; g++) {
                mx0 = fmaxf(mx0, fmaxf(c[g][0], c[g][1]));
                mx1 = fmaxf(mx1, fmaxf(c[g][2], c[g][3]));
            }
#pragma unroll
            for (int off = 1; off < 4; off <<= 1) {
                mx0 = fmaxf(mx0, __shfl_xor_sync(0xffffffffu, mx0, off));
                mx1 = fmaxf(mx1, __shfl_xor_sync(0xffffffffu, mx1, off));
            }
            float mn0 = fmaxf(m0, mx0), mn1 = fmaxf(m1, mx1);
            float al0 = __expf(m0 - mn0), al1 = __expf(m1 - mn1);
            float rs0 = 0.f, rs1 = 0.f;
#pragma unroll
            for (int g = 0; g < 4; g++) {
                c[g][0] = __expf(c[g][0] - mn0); rs0 += c[g][0];
                c[g][1] = __expf(c[g][1] - mn0); rs0 += c[g][1];
                c[g][2] = __expf(c[g][2] - mn1); rs1 += c[g][2];
                c[g][3] = __expf(c[g][3] - mn1); rs1 += c[g][3];
            }
#pragma unroll
            for (int off = 1; off < 4; off <<= 1) {
                rs0 += __shfl_xor_sync(0xffffffffu, rs0, off);
                rs1 += __shfl_xor_sync(0xffffffffu, rs1, off);
            }
            l0 = l0 * al0 + rs0; l1 = l1 * al1 + rs1;
            m0 = mn0; m1 = mn1;
#pragma unroll
            for (int g = 0; g < 16; g++) {
                o[g][0] *= al0; o[g][1] *= al0;
                o[g][2] *= al1; o[g][3] *= al1;
            }

            // O += P * Vh  (single pass)
#pragma unroll
            for (int kc = 0; kc < 2; kc++) {
                uint32_t aph[4];
                aph[0] = pack_h2(c[2 * kc][0],     c[2 * kc][1]);
                aph[1] = pack_h2(c[2 * kc][2],     c[2 * kc][3]);
                aph[2] = pack_h2(c[2 * kc + 1][0], c[2 * kc + 1][1]);
                aph[3] = pack_h2(c[2 * kc + 1][2], c[2 * kc + 1][3]);
#pragma unroll
                for (int ng = 0; ng < 8; ng++) {
                    uint32_t vh4[4];
                    ldsm4t(vst + vfrel + kc * (16 * VSTRB) + ng * 32, vh4);
                    MMAH(o[2 * ng],     aph, vh4[0], vh4[1]);
                    MMAH(o[2 * ng + 1], aph, vh4[2], vh4[3]);
                }
            }
        }
        buf++; if (buf >= 3) buf = 0;
    }

    const int rl0 = wid * 16 + (lane >> 2);
    if (part < 0) {
        float inv0 = 1.0f / l0, inv1 = 1.0f / l1;
        int row0 = qbase + rl0;
#pragma unroll
        for (int g = 0; g < 16; g++) {
            int col = h * VH_D + g * 8 + (lane & 3) * 2;
            *(uint32_t*)(O + (size_t)row0 * ATTN_N + col) =
                pack_h2(o[g][0] * inv0, o[g][1] * inv0);
            *(uint32_t*)(O + (size_t)(row0 + 8) * ATTN_N + col) =
                pack_h2(o[g][2] * inv1, o[g][3] * inv1);
        }
    } else {
        const int sb = (h * 8 + (qb - 8)) * 2 + part;
        const size_t ob0 = ((size_t)sb * 128 + rl0) * 128;
        const size_t ob1 = ((size_t)sb * 128 + rl0 + 8) * 128;
#pragma unroll
        for (int g = 0; g < 16; g++) {
            int col = g * 8 + (lane & 3) * 2;
            *(float2*)(g_fo + ob0 + col) = make_float2(o[g][0], o[g][1]);
            *(float2*)(g_fo + ob1 + col) = make_float2(o[g][2], o[g][3]);
        }
        if ((lane & 3) == 0) {
            g_fm[sb * 128 + rl0] = m0;     g_fl[sb * 128 + rl0] = l0;
            g_fm[sb * 128 + rl0 + 8] = m1; g_fl[sb * 128 + rl0 + 8] = l1;
        }
    }
}

// ---------------- flash split-KV merge ----------------
__global__ void __launch_bounds__(256) flash_merge(fp16* __restrict__ O)
{
    int t = threadIdx.x;
    int rl = blockIdx.x * 4 + (t >> 6);
    int h = rl >> 10;
    int rem = rl & 1023;
    int qbs = rem >> 7;
    int row = rem & 127;
    int c = (t & 63) * 2;

    int i0 = ((h * 8 + qbs) * 2 + 0) * 128 + row;
    int i1 = ((h * 8 + qbs) * 2 + 1) * 128 + row;
    float m0 = g_fm[i0], m1 = g_fm[i1];
    float l0 = g_fl[i0], l1 = g_fl[i1];
    float m = fmaxf(m0, m1);
    float w0 = __expf(m0 - m), w1 = __expf(m1 - m);
    float inv = 1.f / (w0 * l0 + w1 * l1);

    float2 a = *(float2*)(g_fo + (size_t)i0 * 128 + c);
    float2 b = *(float2*)(g_fo + (size_t)i1 * 128 + c);
    size_t off = (size_t)((qbs + 8) * 128 + row) * ATTN_N + h * VH_D + c;
    *(uint32_t*)(O + off) = pack_h2((w0 * a.x + w1 * b.x) * inv,
                                    (w0 * a.y + w1 * b.y) * inv);
}

// ---------------- launch ----------------
extern "C" void kernel_launch(void* const* d_in, const int* in_sizes, int n_in,
                              void* d_out, int out_size)
{
    const float* x          = (const float*)d_in[0];
    const float* fcos       = (const float*)d_in[2];
    const float* fsin       = (const float*)d_in[3];
    const float* wq_down_w  = (const float*)d_in[5];
    const float* wq_down_b  = (const float*)d_in[6];
    const float* q_norm_w   = (const float*)d_in[7];
    const float* wq_up_w    = (const float*)d_in[8];
    const float* wq_up_b    = (const float*)d_in[9];
    const float* wkv_down_w = (const float*)d_in[10];
    const float* wkv_down_b = (const float*)d_in[11];
    const float* kv_norm_w  = (const float*)d_in[12];
    const float* wkv_up_w   = (const float*)d_in[13];
    const float* wkv_up_b   = (const float*)d_in[14];
    const float* wo_w       = (const float*)d_in[15];
    const float* wo_b       = (const float*)d_in[16];
    float* out = (float*)d_out;

    float *qdown, *kv;
    fp16 *xh, *qdnh, *kvnh, *attnh, *qfh, *kfh, *kfl, *vfh;
    fp16 *wqdh, *wqdl, *wkvdh, *wkvdl, *wquh, *wqul, *wkvuh, *wkvul, *woh, *wol;
    cudaGetSymbolAddress((void**)&qdown, g_qdown);
    cudaGetSymbolAddress((void**)&kv,    g_kv);
    cudaGetSymbolAddress((void**)&xh, g_xh);
    cudaGetSymbolAddress((void**)&qdnh, g_qdnh);
    cudaGetSymbolAddress((void**)&kvnh, g_kvnh);
    cudaGetSymbolAddress((void**)&attnh, g_attnh);
    cudaGetSymbolAddress((void**)&qfh, g_qfh);
    cudaGetSymbolAddress((void**)&kfh, g_kfh);     cudaGetSymbolAddress((void**)&kfl, g_kfl);
    cudaGetSymbolAddress((void**)&vfh, g_vfh);
    cudaGetSymbolAddress((void**)&wqdh, g_wqdh);   cudaGetSymbolAddress((void**)&wqdl, g_wqdl);
    cudaGetSymbolAddress((void**)&wkvdh, g_wkvdh); cudaGetSymbolAddress((void**)&wkvdl, g_wkvdl);
    cudaGetSymbolAddress((void**)&wquh, g_wquh);   cudaGetSymbolAddress((void**)&wqul, g_wqul);
    cudaGetSymbolAddress((void**)&wkvuh, g_wkvuh); cudaGetSymbolAddress((void**)&wkvul, g_wkvul);
    cudaGetSymbolAddress((void**)&woh, g_woh);     cudaGetSymbolAddress((void**)&wol, g_wol);

    cudaFuncSetAttribute(gemm_mma2, cudaFuncAttributeMaxDynamicSharedMemorySize, GM_SMEM);
    cudaFuncSetAttribute(mla_flash_mma, cudaFuncAttributeMaxDynamicSharedMemorySize, FLASH_SMEM);

    // one-shot convert: x (hi) + all 5 weights (hi+lo)
    split_all<<<19072, 256>>>(x, wq_down_w, wkv_down_w, wq_up_w, wkv_up_w, wo_w);

    // batched down projections: q_down (mode 0) + kv_down (mode 3)
    gemm_mma2<<<dim3(12 + 5, S_LEN / 128), 512, GM_SMEM>>>(
        xh, wqdh, wqdl, wq_down_b, qdown, QLORA, D_DIM, 0, 12,
        xh, wkvdh, wkvdl, wkv_down_b, kv, KVD, D_DIM, 3,
        fcos, fsin);

    // fused dual rmsnorm
    mla_rmsnorm2<<<2 * S_LEN, 256>>>(q_norm_w, kv_norm_w);

    // batched up projections: q_up (mode 1) + kv_up (mode 2)
    gemm_mma2<<<dim3(24 + 32, S_LEN / 128), 512, GM_SMEM>>>(
        qdnh, wquh, wqul, wq_up_b, qdown, QUP_N, QLORA, 1, 24,
        kvnh, wkvuh, wkvul, wkv_up_b, qdown, KVUP_N, KVLORA, 2,
        fcos, fsin);

    // flash attention with split-KV (384 CTAs, size-descending, 3-stage pipeline)
    mla_flash_mma<<<dim3(24, H_N), 256, FLASH_SMEM>>>(
        qfh, kfh, kfl, vfh, attnh);
    flash_merge<<<4096, 256>>>(attnh);

    // output projection (mode 0; second slot inert)
    gemm_mma2<<<dim3(16, S_LEN / 128), 512, GM_SMEM>>>(
        attnh, woh, wol, wo_b, out, D_DIM, ATTN_N, 0, 16,
        attnh, woh, wol, wo_b, out, D_DIM, ATTN_N, 0,
        fcos, fsin);
}

// round 16
// speedup vs baseline: 1.4153x; 1.3584x over previous
#include <cuda_runtime.h>
#include <cuda_fp16.h>
#include <cstdint>
#include <math.h>

// ---------------- problem constants ----------------
#define S_LEN   2048
#define D_DIM   2048
#define H_N     16
#define NOPE_D  128
#define ROPE_D  64
#define QK_D    192
#define VH_D    128
#define QLORA   1536
#define KVLORA  512
#define KVD     576
#define QUP_N   (H_N*QK_D)            // 3072
#define KVUP_N  (H_N*(NOPE_D+VH_D))   // 4096
#define ATTN_N  (H_N*VH_D)            // 2048

typedef __half fp16;

// ---------------- scratch ----------------
__device__ float g_qdown[S_LEN*QLORA];
__device__ float g_kv   [S_LEN*KVD];

// activations: fp16 hi only
__device__ fp16 g_xh[S_LEN*D_DIM];
__device__ fp16 g_qdnh[S_LEN*QLORA];
__device__ fp16 g_kvnh[S_LEN*KVLORA];
__device__ fp16 g_attnh[S_LEN*ATTN_N];
__device__ fp16 g_qfh[S_LEN*QUP_N];
// K (flash B-side): hi + lo (protects logits);  V: hi only
__device__ fp16 g_kfh[S_LEN*QUP_N],  g_kfl[S_LEN*QUP_N];
__device__ fp16 g_vfh[S_LEN*ATTN_N];
// weights: fp16 hi only (pure-fp16 GEMMs; quadrature-budgeted)
__device__ fp16 g_wqdh[QLORA*D_DIM];
__device__ fp16 g_wkvdh[KVD*D_DIM];
__device__ fp16 g_wquh[QUP_N*QLORA];
__device__ fp16 g_wkvuh[KVUP_N*KVLORA];
__device__ fp16 g_woh[D_DIM*ATTN_N];

// flash split-KV scratch
__device__ float g_fo[16*8*2*128*128];
__device__ float g_fm[16*8*2*128];
__device__ float g_fl[16*8*2*128];

// flash CTA schedule: descending work size
__device__ const int c_qb[24] = {15,15,7,14,14,13,13,6,12,12,11,11,5,10,10,9,9,4,8,8,3,2,1,0};
__device__ const int c_pt[24] = {0,1,-1,0,1,0,1,-1,0,1,0,1,-1,0,1,0,1,-1,0,1,-1,-1,-1,-1};

// ---------------- PTX helpers (sm_80+ PTX only; compute_103-safe) ----------------
__device__ __forceinline__ uint32_t smem_u32(const void* p) {
    uint32_t a;
    asm("{ .reg .u64 t; cvta.to.shared.u64 t, %1; cvt.u32.u64 %0, t; }" : "=r"(a) : "l"(p));
    return a;
}

#define CP_ASYNC16(dst, src, sz) \
    asm volatile("cp.async.cg.shared.global [%0], [%1], 16, %2;" \
        :: "r"(dst), "l"(src), "r"(sz) : "memory")
#define CP_COMMIT()  asm volatile("cp.async.commit_group;" ::: "memory")
#define CP_WAIT(n)   asm volatile("cp.async.wait_group %0;" :: "n"(n) : "memory")

__device__ __forceinline__ void ldsm4(uint32_t addr, uint32_t* f) {
    asm volatile("ldmatrix.sync.aligned.m8n8.x4.shared.b16 {%0,%1,%2,%3}, [%4];"
        : "=r"(f[0]), "=r"(f[1]), "=r"(f[2]), "=r"(f[3]) : "r"(addr));
}
__device__ __forceinline__ void ldsm4t(uint32_t addr, uint32_t* f) {
    asm volatile("ldmatrix.sync.aligned.m8n8.x4.trans.shared.b16 {%0,%1,%2,%3}, [%4];"
        : "=r"(f[0]), "=r"(f[1]), "=r"(f[2]), "=r"(f[3]) : "r"(addr));
}

#define MMAH(d, a, b0, b1) \
    asm volatile("mma.sync.aligned.m16n8k16.row.col.f32.f16.f16.f32 " \
        "{%0,%1,%2,%3}, {%4,%5,%6,%7}, {%8,%9}, {%0,%1,%2,%3};" \
        : "+f"((d)[0]), "+f"((d)[1]), "+f"((d)[2]), "+f"((d)[3]) \
        : "r"((a)[0]), "r"((a)[1]), "r"((a)[2]), "r"((a)[3]), "r"(b0), "r"(b1))

__device__ __forceinline__ uint32_t off16(int r, int c) {
    return (uint32_t)(r * 4 + ((((r >> 1) & 3) ^ c)));
}
__device__ __forceinline__ uint32_t pack_h2(float a, float b) {
    __half2 t = __floats2half2_rn(a, b);
    return *(uint32_t*)&t;
}
__device__ __forceinline__ void split2h(float a, float b, uint32_t& h, uint32_t& l) {
    __half2 hh = __floats2half2_rn(a, b);
    float ar = a - __low2float(hh), br = b - __high2float(hh);
    h = *(uint32_t*)&hh;
    l = pack_h2(ar, br);
}

// ---------------- one-shot convert: x + all weights -> fp16 hi ----------------
__global__ void __launch_bounds__(256) split_all(
    const float* __restrict__ x,  const float* __restrict__ wqd,
    const float* __restrict__ wkd, const float* __restrict__ wqu,
    const float* __restrict__ wku, const float* __restrict__ wo)
{
    int b = blockIdx.x;
    const float* src; fp16* dh; int i;
    if (b < 4096)       { src = x;   dh = g_xh;    i = b * 256; }
    else if (b < 7168)  { src = wqd; dh = g_wqdh;  i = (b - 4096) * 256; }
    else if (b < 8320)  { src = wkd; dh = g_wkvdh; i = (b - 7168) * 256; }
    else if (b < 12928) { src = wqu; dh = g_wquh;  i = (b - 8320) * 256; }
    else if (b < 14976) { src = wku; dh = g_wkvuh; i = (b - 12928) * 256; }
    else                { src = wo;  dh = g_woh;   i = (b - 14976) * 256; }
    i += threadIdx.x;
    float4 v = ((const float4*)src)[i];
    ((uint2*)dh)[i] = make_uint2(pack_h2(v.x, v.y), pack_h2(v.z, v.w));
}

// ---------------- fp16 1-pass NT GEMM: 512 threads, 16 warps, warp tile 32x32 ----------------
// 3-stage cp.async pipeline, ONE __syncthreads per k-iteration.
// C = Ah Bh^T + bias.
// mode 0: f32 C; mode 1: q_up rope+round->g_qfh; mode 2: kv_up split K / round V;
// mode 3: kv_down f32 C + k_pe rope/broadcast split->kf
#define GM_SMEM (3*16384)   // 3 stages x (A 8KB, B 8KB)

__global__ void __launch_bounds__(512, 1) gemm_mma2(
    const fp16* __restrict__ Ah0, const fp16* __restrict__ Bh0,
    const float* __restrict__ bias0, float* __restrict__ C0, int N0, int K0, int mode0, int NX0,
    const fp16* __restrict__ Ah1, const fp16* __restrict__ Bh1,
    const float* __restrict__ bias1, float* __restrict__ C1, int N1, int K1, int mode1,
    const float* __restrict__ fc, const float* __restrict__ fs)
{
    extern __shared__ __align__(1024) char sm[];
    const uint32_t smb = smem_u32(sm);

    const fp16 *Ah, *Bh;
    const float* bias;
    float* C;
    int N, K, mode, bx = blockIdx.x;
    if (bx < NX0) {
        Ah = Ah0; Bh = Bh0; bias = bias0; C = C0; N = N0; K = K0; mode = mode0;
    } else {
        bx -= NX0;
        Ah = Ah1; Bh = Bh1; bias = bias1; C = C1; N = N1; K = K1; mode = mode1;
    }

    const int tid = threadIdx.x;
    const int lane = tid & 31;
    const int wid = tid >> 5;          // 0..15
    const int warp_m = wid & 3;
    const int warp_n = wid >> 2;
    const int brow = blockIdx.y * 128;
    const int bcol = bx * 128;

    const int r0g = tid >> 2;
    const int c0g = tid & 3;

    uint32_t aoff[2][2], boff[2][2];
#pragma unroll
    for (int mt = 0; mt < 2; mt++)
#pragma unroll
        for (int ks = 0; ks < 2; ks++) {
            int rr = warp_m * 32 + mt * 16 + (lane & 15);
            int cc = ks * 2 + (lane >> 4);
            aoff[mt][ks] = off16(rr, cc) * 16;
        }
#pragma unroll
    for (int g = 0; g < 2; g++)
#pragma unroll
        for (int ks = 0; ks < 2; ks++) {
            int rr = warp_n * 32 + g * 16 + (lane & 15);
            int cc = ks * 2 + (lane >> 4);
            boff[g][ks] = off16(rr, cc) * 16;
        }

    float acc[2][4][4];
#pragma unroll
    for (int i = 0; i < 2; i++)
#pragma unroll
        for (int j = 0; j < 4; j++)
#pragma unroll
            for (int k = 0; k < 4; k++) acc[i][j][k] = 0.f;

    const int KT = K >> 5;

    auto load_stage = [&](int s, int k0) {
        uint32_t base = smb + s * 16384;
        uint32_t doff = off16(r0g, c0g) * 16;
        size_t ga = (size_t)(brow + r0g) * K + k0 + c0g * 8;
        CP_ASYNC16(base + doff, Ah + ga, 16);
        int gr = bcol + r0g;
        int ok = (gr < N) ? 16 : 0;
        size_t gb = (size_t)(ok ? gr : 0) * K + k0 + c0g * 8;
        CP_ASYNC16(base + 8192 + doff, Bh + gb, ok);
        CP_COMMIT();
    };

    load_stage(0, 0);
    load_stage(1, 32);

    uint32_t af[2][2][4], bfr[2][2][4];

    int buf = 0;
    for (int kt = 0; kt < KT; kt++) {
        if (kt + 1 < KT) CP_WAIT(1); else CP_WAIT(0);
        __syncthreads();
        if (kt + 2 < KT) {
            int nb = buf + 2; if (nb >= 3) nb -= 3;
            load_stage(nb, (kt + 2) * 32);
        }

        uint32_t st = smb + buf * 16384;

#pragma unroll
        for (int mt = 0; mt < 2; mt++)
#pragma unroll
            for (int ks = 0; ks < 2; ks++)
                ldsm4(st + aoff[mt][ks], af[mt][ks]);
#pragma unroll
        for (int g = 0; g < 2; g++)
#pragma unroll
            for (int ks = 0; ks < 2; ks++)
                ldsm4(st + 8192 + boff[g][ks], bfr[g][ks]);

#pragma unroll
        for (int mt = 0; mt < 2; mt++)
#pragma unroll
            for (int nt = 0; nt < 4; nt++) {
                int g = nt >> 1, hf = nt & 1;
#pragma unroll
                for (int ks = 0; ks < 2; ks++)
                    MMAH(acc[mt][nt], af[mt][ks],
                         bfr[g][ks][hf], bfr[g][ks][hf + 2]);
            }

        buf++; if (buf >= 3) buf = 0;
    }

    // ---- fused epilogues ----
#pragma unroll
    for (int mt = 0; mt < 2; mt++) {
        int row = brow + warp_m * 32 + mt * 16 + (lane >> 2);
#pragma unroll
        for (int nt = 0; nt < 4; nt++) {
            int col = bcol + warp_n * 32 + nt * 8 + (lane & 3) * 2;
            if (col >= N) continue;
            float b0 = bias[col], b1 = bias[col + 1];
            float v00 = acc[mt][nt][0] + b0, v01 = acc[mt][nt][1] + b1;
            float v10 = acc[mt][nt][2] + b0, v11 = acc[mt][nt][3] + b1;

            if (mode == 0) {
                *(float2*)(C + (size_t)row * N + col) = make_float2(v00, v01);
                *(float2*)(C + (size_t)(row + 8) * N + col) = make_float2(v10, v11);
            } else if (mode == 1) {
                int h = col / QK_D, d = col - h * QK_D;
                if (d >= NOPE_D) {
                    int p0 = (d - NOPE_D) >> 1;
                    float c0 = fc[row * 32 + p0], s0 = fs[row * 32 + p0];
                    float t0 = v00 * c0 - v01 * s0;
                    v01 = v00 * s0 + v01 * c0; v00 = t0;
                    float c1 = fc[(row + 8) * 32 + p0], s1 = fs[(row + 8) * 32 + p0];
                    float t1 = v10 * c1 - v11 * s1;
                    v11 = v10 * s1 + v11 * c1; v10 = t1;
                }
                size_t o0 = ((size_t)row * H_N + h) * QK_D + d;
                size_t o1 = ((size_t)(row + 8) * H_N + h) * QK_D + d;
                *(uint32_t*)(g_qfh + o0) = pack_h2(v00, v01);
                *(uint32_t*)(g_qfh + o1) = pack_h2(v10, v11);
            } else if (mode == 2) {
                int h = col >> 8, dd = col & 255;
                if (dd < NOPE_D) {
                    uint32_t hh, ll;
                    size_t o0 = ((size_t)row * H_N + h) * QK_D + dd;
                    size_t o1 = ((size_t)(row + 8) * H_N + h) * QK_D + dd;
                    split2h(v00, v01, hh, ll);
                    *(uint32_t*)(g_kfh + o0) = hh; *(uint32_t*)(g_kfl + o0) = ll;
                    split2h(v10, v11, hh, ll);
                    *(uint32_t*)(g_kfh + o1) = hh; *(uint32_t*)(g_kfl + o1) = ll;
                } else {
                    size_t o0 = ((size_t)row * H_N + h) * VH_D + (dd - NOPE_D);
                    size_t o1 = ((size_t)(row + 8) * H_N + h) * VH_D + (dd - NOPE_D);
                    *(uint32_t*)(g_vfh + o0) = pack_h2(v00, v01);
                    *(uint32_t*)(g_vfh + o1) = pack_h2(v10, v11);
                }
            } else {  // mode 3: kv_down
                *(float2*)(C + (size_t)row * N + col) = make_float2(v00, v01);
                *(float2*)(C + (size_t)(row + 8) * N + col) = make_float2(v10, v11);
                if (col >= KVLORA) {
                    int d = col - KVLORA;
                    int p0 = d >> 1;
                    float c0 = fc[row * 32 + p0], s0 = fs[row * 32 + p0];
                    float r00 = v00 * c0 - v01 * s0;
                    float r01 = v00 * s0 + v01 * c0;
                    float c1 = fc[(row + 8) * 32 + p0], s1 = fs[(row + 8) * 32 + p0];
                    float r10 = v10 * c1 - v11 * s1;
                    float r11 = v10 * s1 + v11 * c1;
                    uint32_t h0p, l0p, h1p, l1p;
                    split2h(r00, r01, h0p, l0p);
                    split2h(r10, r11, h1p, l1p);
#pragma unroll
                    for (int hh = 0; hh < H_N; hh++) {
                        size_t o0 = ((size_t)row * H_N + hh) * QK_D + NOPE_D + d;
                        size_t o1 = ((size_t)(row + 8) * H_N + hh) * QK_D + NOPE_D + d;
                        *(uint32_t*)(g_kfh + o0) = h0p; *(uint32_t*)(g_kfl + o0) = l0p;
                        *(uint32_t*)(g_kfh + o1) = h1p; *(uint32_t*)(g_kfl + o1) = l1p;
                    }
                }
            }
        }
    }
}

// ---------------- fused dual RMSNorm -> fp16 (hi only) ----------------
__global__ void __launch_bounds__(256) mla_rmsnorm2(
    const float* __restrict__ qnw, const float* __restrict__ kvnw)
{
    int row = blockIdx.x;
    const float* x; const float* w; fp16* y; int L;
    if (row < S_LEN) {
        x = g_qdown + (size_t)row * QLORA; w = qnw;
        y = g_qdnh + (size_t)row * QLORA; L = QLORA;
    } else {
        row -= S_LEN;
        x = g_kv + (size_t)row * KVD; w = kvnw;
        y = g_kvnh + (size_t)row * KVLORA; L = KVLORA;
    }
    float ss = 0.f;
    for (int c = threadIdx.x; c < L; c += blockDim.x) {
        float v = x[c];
        ss = fmaf(v, v, ss);
    }
#pragma unroll
    for (int o = 16; o; o >>= 1) ss += __shfl_xor_sync(0xffffffffu, ss, o);
    __shared__ float red[8];
    __shared__ float s_inv;
    if ((threadIdx.x & 31) == 0) red[threadIdx.x >> 5] = ss;
    __syncthreads();
    if (threadIdx.x == 0) {
        float t = 0.f;
#pragma unroll
        for (int i = 0; i < 8; i++) t += red[i];
        s_inv = rsqrtf(t / (float)L + 1e-6f);
    }
    __syncthreads();
    float inv = s_inv;
    for (int c = threadIdx.x; c < L / 2; c += blockDim.x) {
        float2 v = ((const float2*)x)[c];
        float2 ww = ((const float2*)w)[c];
        *(uint32_t*)(y + c * 2) = pack_h2(ww.x * (v.x * inv), ww.y * (v.y * inv));
    }
}

// ---------------- fp16 flash attention (causal, split-KV; K hi+lo, V hi only) ----------------
// 3-stage K/V pipeline, one __syncthreads per key-block iteration.
#define FQ 128
#define FK 32
#define QSTRB 400
#define VSTRB 272
#define SQ  0
#define SK  51200            // 3 stages x (Kh 12800 + Kl 12800)
#define KSTAGE 25600
#define SV  128000           // 3 stages x (Vh 8704)
#define VSTAGE 8704
#define FLASH_SMEM 154112

__global__ void __launch_bounds__(256, 1) mla_flash_mma(
    const fp16* __restrict__ Qh,
    const fp16* __restrict__ Kh, const fp16* __restrict__ Kl,
    const fp16* __restrict__ Vh,
    fp16* __restrict__ O)
{
    extern __shared__ __align__(1024) char fsmem[];
    const uint32_t smb = smem_u32(fsmem);

    const int h = blockIdx.y;
    const int qb = c_qb[blockIdx.x];
    const int part = c_pt[blockIdx.x];
    const int qbase = qb * FQ;
    const int tid = threadIdx.x;
    const int lane = tid & 31;
    const int wid = tid >> 5;
    const int row_min = qbase + wid * 16;

    const int u_total = 4 * (qb + 1);
    const int u_cnt = (part < 0) ? u_total : (u_total >> 1);
    const int u0 = (part < 0) ? 0 : part * u_cnt;

    for (int i = tid; i < FQ * 24; i += 256) {
        int r = i / 24, c = i % 24;
        size_t go = ((size_t)(qbase + r) * H_N + h) * QK_D + c * 8;
        CP_ASYNC16(smb + SQ + (uint32_t)(r * QSTRB + c * 16), Qh + go, 16);
    }
    CP_COMMIT();

    auto load_kv = [&](int s, int kbase) {
        uint32_t kbp = smb + SK + s * KSTAGE;
        uint32_t vbp = smb + SV + s * VSTAGE;
#pragma unroll
        for (int it = 0; it < 3; it++) {
            int i = tid + it * 256;
            int r = i / 24, c = i % 24;
            size_t go = ((size_t)(kbase + r) * H_N + h) * QK_D + c * 8;
            uint32_t so = (uint32_t)(r * QSTRB + c * 16);
            CP_ASYNC16(kbp + so, Kh + go, 16);
            CP_ASYNC16(kbp + 12800 + so, Kl + go, 16);
        }
        {
            int i = tid;
            int r = i >> 4, c = i & 15;
            size_t go = ((size_t)(kbase + r) * H_N + h) * VH_D + c * 8;
            CP_ASYNC16(vbp + (uint32_t)(r * VSTRB + c * 16), Vh + go, 16);
            i = tid + 256;
            r = i >> 4; c = i & 15;
            go = ((size_t)(kbase + r) * H_N + h) * VH_D + c * 8;
            CP_ASYNC16(vbp + (uint32_t)(r * VSTRB + c * 16), Vh + go, 16);
        }
        CP_COMMIT();
    };

    const uint32_t qfb = smb + SQ + (uint32_t)((wid * 16 + (lane & 15)) * QSTRB + (lane >> 4) * 16);
    const uint32_t kfrel = (uint32_t)((lane & 15) * QSTRB + (lane >> 4) * 16);
    const uint32_t vfrel = (uint32_t)((lane & 15) * VSTRB + (lane >> 4) * 16);

    float o[16][4];
#pragma unroll
    for (int g = 0; g < 16; g++)
#pragma unroll
        for (int j = 0; j < 4; j++) o[g][j] = 0.f;
    float m0 = -1e30f, m1 = -1e30f, l0 = 0.f, l1 = 0.f;
    const float scale = 0.07216878364870322f;

    load_kv(0, u0 * FK);
    if (u_cnt > 1) load_kv(1, (u0 + 1) * FK);

    int buf = 0;
    for (int kb = 0; kb < u_cnt; kb++) {
        const int kbase = (u0 + kb) * FK;
        if (kb + 1 < u_cnt) CP_WAIT(1); else CP_WAIT(0);
        __syncthreads();
        if (kb + 2 < u_cnt) {
            int nb = buf + 2; if (nb >= 3) nb -= 3;
            load_kv(nb, (u0 + kb + 2) * FK);
        }

        if (kbase <= row_min) {
            uint32_t kst = smb + SK + buf * KSTAGE;
            uint32_t vst = smb + SV + buf * VSTAGE;

            float c[4][4];
#pragma unroll
            for (int g = 0; g < 4; g++)
#pragma unroll
                for (int j = 0; j < 4; j++) c[g][j] = 0.f;

#pragma unroll
            for (int ks = 0; ks < 12; ks++) {
                uint32_t ah[4];
                ldsm4(qfb + ks * 32, ah);
#pragma unroll
                for (int gg = 0; gg < 2; gg++) {
                    uint32_t bh[4], bl[4];
                    ldsm4(kst + kfrel + gg * (16 * QSTRB) + ks * 32, bh);
                    ldsm4(kst + 12800 + kfrel + gg * (16 * QSTRB) + ks * 32, bl);
                    MMAH(c[2 * gg],     ah, bh[0], bh[2]);
                    MMAH(c[2 * gg + 1], ah, bh[1], bh[3]);
                    MMAH(c[2 * gg],     ah, bl[0], bl[2]);
                    MMAH(c[2 * gg + 1], ah, bl[1], bl[3]);
                }
            }

            const int row0 = row_min + (lane >> 2);
            const bool needmask = (kbase + FK - 1 > row_min);
#pragma unroll
            for (int g = 0; g < 4; g++) {
                int col = kbase + g * 8 + (lane & 3) * 2;
#pragma unroll
                for (int j = 0; j < 4; j++) {
                    float v = c[g][j] * scale;
                    if (needmask) {
                        int cc = col + (j & 1);
                        int rr = row0 + ((j >> 1) << 3);
                        if (cc > rr) v = -1e30f;
                    }
                    c[g][j] = v;
                }
            }

            float mx0 = -1e30f, mx1 = -1e30f;
#pragma unroll
            for (int g = 0; g < 4; g++) {
                mx0 = fmaxf(mx0, fmaxf(c[g][0], c[g][1]));
                mx1 = fmaxf(mx1, fmaxf(c[g][2], c[g][3]));
            }
#pragma unroll
            for (int off = 1; off < 4; off <<= 1) {
                mx0 = fmaxf(mx0, __shfl_xor_sync(0xffffffffu, mx0, off));
                mx1 = fmaxf(mx1, __shfl_xor_sync(0xffffffffu, mx1, off));
            }
            float mn0 = fmaxf(m0, mx0), mn1 = fmaxf(m1, mx1);
            float al0 = __expf(m0 - mn0), al1 = __expf(m1 - mn1);
            float rs0 = 0.f, rs1 = 0.f;
#pragma unroll
            for (int g = 0; g < 4; g++) {
                c[g][0] = __expf(c[g][0] - mn0); rs0 += c[g][0];
                c[g][1] = __expf(c[g][1] - mn0); rs0 += c[g][1];
                c[g][2] = __expf(c[g][2] - mn1); rs1 += c[g][2];
                c[g][3] = __expf(c[g][3] - mn1); rs1 += c[g][3];
            }
#pragma unroll
            for (int off = 1; off < 4; off <<= 1) {
                rs0 += __shfl_xor_sync(0xffffffffu, rs0, off);
                rs1 += __shfl_xor_sync(0xffffffffu, rs1, off);
            }
            l0 = l0 * al0 + rs0; l1 = l1 * al1 + rs1;
            m0 = mn0; m1 = mn1;
#pragma unroll
            for (int g = 0; g < 16; g++) {
                o[g][0] *= al0; o[g][1] *= al0;
                o[g][2] *= al1; o[g][3] *= al1;
            }

            // O += P * Vh  (single pass)
#pragma unroll
            for (int kc = 0; kc < 2; kc++) {
                uint32_t aph[4];
                aph[0] = pack_h2(c[2 * kc][0],     c[2 * kc][1]);
                aph[1] = pack_h2(c[2 * kc][2],     c[2 * kc][3]);
                aph[2] = pack_h2(c[2 * kc + 1][0], c[2 * kc + 1][1]);
                aph[3] = pack_h2(c[2 * kc + 1][2], c[2 * kc + 1][3]);
#pragma unroll
                for (int ng = 0; ng < 8; ng++) {
                    uint32_t vh4[4];
                    ldsm4t(vst + vfrel + kc * (16 * VSTRB) + ng * 32, vh4);
                    MMAH(o[2 * ng],     aph, vh4[0], vh4[1]);
                    MMAH(o[2 * ng + 1], aph, vh4[2], vh4[3]);
                }
            }
        }
        buf++; if (buf >= 3) buf = 0;
    }

    const int rl0 = wid * 16 + (lane >> 2);
    if (part < 0) {
        float inv0 = 1.0f / l0, inv1 = 1.0f / l1;
        int row0 = qbase + rl0;
#pragma unroll
        for (int g = 0; g < 16; g++) {
            int col = h * VH_D + g * 8 + (lane & 3) * 2;
            *(uint32_t*)(O + (size_t)row0 * ATTN_N + col) =
                pack_h2(o[g][0] * inv0, o[g][1] * inv0);
            *(uint32_t*)(O + (size_t)(row0 + 8) * ATTN_N + col) =
                pack_h2(o[g][2] * inv1, o[g][3] * inv1);
        }
    } else {
        const int sb = (h * 8 + (qb - 8)) * 2 + part;
        const size_t ob0 = ((size_t)sb * 128 + rl0) * 128;
        const size_t ob1 = ((size_t)sb * 128 + rl0 + 8) * 128;
#pragma unroll
        for (int g = 0; g < 16; g++) {
            int col = g * 8 + (lane & 3) * 2;
            *(float2*)(g_fo + ob0 + col) = make_float2(o[g][0], o[g][1]);
            *(float2*)(g_fo + ob1 + col) = make_float2(o[g][2], o[g][3]);
        }
        if ((lane & 3) == 0) {
            g_fm[sb * 128 + rl0] = m0;     g_fl[sb * 128 + rl0] = l0;
            g_fm[sb * 128 + rl0 + 8] = m1; g_fl[sb * 128 + rl0 + 8] = l1;
        }
    }
}

// ---------------- flash split-KV merge ----------------
__global__ void __launch_bounds__(256) flash_merge(fp16* __restrict__ O)
{
    int t = threadIdx.x;
    int rl = blockIdx.x * 4 + (t >> 6);
    int h = rl >> 10;
    int rem = rl & 1023;
    int qbs = rem >> 7;
    int row = rem & 127;
    int c = (t & 63) * 2;

    int i0 = ((h * 8 + qbs) * 2 + 0) * 128 + row;
    int i1 = ((h * 8 + qbs) * 2 + 1) * 128 + row;
    float m0 = g_fm[i0], m1 = g_fm[i1];
    float l0 = g_fl[i0], l1 = g_fl[i1];
    float m = fmaxf(m0, m1);
    float w0 = __expf(m0 - m), w1 = __expf(m1 - m);
    float inv = 1.f / (w0 * l0 + w1 * l1);

    float2 a = *(float2*)(g_fo + (size_t)i0 * 128 + c);
    float2 b = *(float2*)(g_fo + (size_t)i1 * 128 + c);
    size_t off = (size_t)((qbs + 8) * 128 + row) * ATTN_N + h * VH_D + c;
    *(uint32_t*)(O + off) = pack_h2((w0 * a.x + w1 * b.x) * inv,
                                    (w0 * a.y + w1 * b.y) * inv);
}

// ---------------- launch ----------------
extern "C" void kernel_launch(void* const* d_in, const int* in_sizes, int n_in,
                              void* d_out, int out_size)
{
    const float* x          = (const float*)d_in[0];
    const float* fcos       = (const float*)d_in[2];
    const float* fsin       = (const float*)d_in[3];
    const float* wq_down_w  = (const float*)d_in[5];
    const float* wq_down_b  = (const float*)d_in[6];
    const float* q_norm_w   = (const float*)d_in[7];
    const float* wq_up_w    = (const float*)d_in[8];
    const float* wq_up_b    = (const float*)d_in[9];
    const float* wkv_down_w = (const float*)d_in[10];
    const float* wkv_down_b = (const float*)d_in[11];
    const float* kv_norm_w  = (const float*)d_in[12];
    const float* wkv_up_w   = (const float*)d_in[13];
    const float* wkv_up_b   = (const float*)d_in[14];
    const float* wo_w       = (const float*)d_in[15];
    const float* wo_b       = (const float*)d_in[16];
    float* out = (float*)d_out;

    float *qdown, *kv;
    fp16 *xh, *qdnh, *kvnh, *attnh, *qfh, *kfh, *kfl, *vfh;
    fp16 *wqdh, *wkvdh, *wquh, *wkvuh, *woh;
    cudaGetSymbolAddress((void**)&qdown, g_qdown);
    cudaGetSymbolAddress((void**)&kv,    g_kv);
    cudaGetSymbolAddress((void**)&xh, g_xh);
    cudaGetSymbolAddress((void**)&qdnh, g_qdnh);
    cudaGetSymbolAddress((void**)&kvnh, g_kvnh);
    cudaGetSymbolAddress((void**)&attnh, g_attnh);
    cudaGetSymbolAddress((void**)&qfh, g_qfh);
    cudaGetSymbolAddress((void**)&kfh, g_kfh);   cudaGetSymbolAddress((void**)&kfl, g_kfl);
    cudaGetSymbolAddress((void**)&vfh, g_vfh);
    cudaGetSymbolAddress((void**)&wqdh, g_wqdh);
    cudaGetSymbolAddress((void**)&wkvdh, g_wkvdh);
    cudaGetSymbolAddress((void**)&wquh, g_wquh);
    cudaGetSymbolAddress((void**)&wkvuh, g_wkvuh);
    cudaGetSymbolAddress((void**)&woh, g_woh);

    cudaFuncSetAttribute(gemm_mma2, cudaFuncAttributeMaxDynamicSharedMemorySize, GM_SMEM);
    cudaFuncSetAttribute(mla_flash_mma, cudaFuncAttributeMaxDynamicSharedMemorySize, FLASH_SMEM);

    // one-shot convert: x + all 5 weights -> fp16 hi
    split_all<<<19072, 256>>>(x, wq_down_w, wkv_down_w, wq_up_w, wkv_up_w, wo_w);

    // batched down projections: q_down (mode 0) + kv_down (mode 3)
    gemm_mma2<<<dim3(12 + 5, S_LEN / 128), 512, GM_SMEM>>>(
        xh, wqdh, wq_down_b, qdown, QLORA, D_DIM, 0, 12,
        xh, wkvdh, wkv_down_b, kv, KVD, D_DIM, 3,
        fcos, fsin);

    // fused dual rmsnorm
    mla_rmsnorm2<<<2 * S_LEN, 256>>>(q_norm_w, kv_norm_w);

    // batched up projections: q_up (mode 1) + kv_up (mode 2)
    gemm_mma2<<<dim3(24 + 32, S_LEN / 128), 512, GM_SMEM>>>(
        qdnh, wquh, wq_up_b, qdown, QUP_N, QLORA, 1, 24,
        kvnh, wkvuh, wkv_up_b, qdown, KVUP_N, KVLORA, 2,
        fcos, fsin);

    // flash attention with split-KV (384 CTAs, size-descending, 3-stage pipeline)
    mla_flash_mma<<<dim3(24, H_N), 256, FLASH_SMEM>>>(
        qfh, kfh, kfl, vfh, attnh);
    flash_merge<<<4096, 256>>>(attnh);

    // output projection (mode 0; second slot inert)
    gemm_mma2<<<dim3(16, S_LEN / 128), 512, GM_SMEM>>>(
        attnh, woh, wo_b, out, D_DIM, ATTN_N, 0, 16,
        attnh, woh, wo_b, out, D_DIM, ATTN_N, 0,
        fcos, fsin);
}

// round 17
// speedup vs baseline: 1.4613x; 1.0325x over previous
#include <cuda_runtime.h>
#include <cuda_fp16.h>
#include <cstdint>
#include <math.h>

// ---------------- problem constants ----------------
#define S_LEN   2048
#define D_DIM   2048
#define H_N     16
#define NOPE_D  128
#define ROPE_D  64
#define QK_D    192
#define VH_D    128
#define QLORA   1536
#define KVLORA  512
#define KVD     576
#define QUP_N   (H_N*QK_D)            // 3072
#define KVUP_N  (H_N*(NOPE_D+VH_D))   // 4096
#define ATTN_N  (H_N*VH_D)            // 2048

typedef __half fp16;

// ---------------- scratch ----------------
__device__ float g_qdown[S_LEN*QLORA];
__device__ float g_kv   [S_LEN*KVD];

// activations: fp16 hi only
__device__ fp16 g_xh[S_LEN*D_DIM];
__device__ fp16 g_qdnh[S_LEN*QLORA];
__device__ fp16 g_kvnh[S_LEN*KVLORA];
__device__ fp16 g_attnh[S_LEN*ATTN_N];
__device__ fp16 g_qfh[S_LEN*QUP_N];
// K (flash B-side): hi + lo (protects logits);  V: hi only
__device__ fp16 g_kfh[S_LEN*QUP_N],  g_kfl[S_LEN*QUP_N];
__device__ fp16 g_vfh[S_LEN*ATTN_N];
// weights: fp16 hi only
__device__ fp16 g_wqdh[QLORA*D_DIM];
__device__ fp16 g_wkvdh[KVD*D_DIM];
__device__ fp16 g_wquh[QUP_N*QLORA];
__device__ fp16 g_wkvuh[KVUP_N*KVLORA];
__device__ fp16 g_woh[D_DIM*ATTN_N];

// flash split-KV scratch
__device__ float g_fo[16*8*2*128*128];
__device__ float g_fm[16*8*2*128];
__device__ float g_fl[16*8*2*128];

// flash CTA schedule: descending work size
__device__ const int c_qb[24] = {15,15,7,14,14,13,13,6,12,12,11,11,5,10,10,9,9,4,8,8,3,2,1,0};
__device__ const int c_pt[24] = {0,1,-1,0,1,0,1,-1,0,1,0,1,-1,0,1,0,1,-1,0,1,-1,-1,-1,-1};

// ---------------- PTX helpers (sm_80+ PTX only; compute_103-safe) ----------------
__device__ __forceinline__ uint32_t smem_u32(const void* p) {
    uint32_t a;
    asm("{ .reg .u64 t; cvta.to.shared.u64 t, %1; cvt.u32.u64 %0, t; }" : "=r"(a) : "l"(p));
    return a;
}

#define CP_ASYNC16(dst, src, sz) \
    asm volatile("cp.async.cg.shared.global [%0], [%1], 16, %2;" \
        :: "r"(dst), "l"(src), "r"(sz) : "memory")
#define CP_COMMIT()  asm volatile("cp.async.commit_group;" ::: "memory")
#define CP_WAIT(n)   asm volatile("cp.async.wait_group %0;" :: "n"(n) : "memory")

__device__ __forceinline__ void ldsm4(uint32_t addr, uint32_t* f) {
    asm volatile("ldmatrix.sync.aligned.m8n8.x4.shared.b16 {%0,%1,%2,%3}, [%4];"
        : "=r"(f[0]), "=r"(f[1]), "=r"(f[2]), "=r"(f[3]) : "r"(addr));
}
__device__ __forceinline__ void ldsm4t(uint32_t addr, uint32_t* f) {
    asm volatile("ldmatrix.sync.aligned.m8n8.x4.trans.shared.b16 {%0,%1,%2,%3}, [%4];"
        : "=r"(f[0]), "=r"(f[1]), "=r"(f[2]), "=r"(f[3]) : "r"(addr));
}

#define MMAH(d, a, b0, b1) \
    asm volatile("mma.sync.aligned.m16n8k16.row.col.f32.f16.f16.f32 " \
        "{%0,%1,%2,%3}, {%4,%5,%6,%7}, {%8,%9}, {%0,%1,%2,%3};" \
        : "+f"((d)[0]), "+f"((d)[1]), "+f"((d)[2]), "+f"((d)[3]) \
        : "r"((a)[0]), "r"((a)[1]), "r"((a)[2]), "r"((a)[3]), "r"(b0), "r"(b1))

__device__ __forceinline__ uint32_t off16(int r, int c) {
    return (uint32_t)(r * 4 + ((((r >> 1) & 3) ^ c)));
}
__device__ __forceinline__ uint32_t pack_h2(float a, float b) {
    __half2 t = __floats2half2_rn(a, b);
    return *(uint32_t*)&t;
}
__device__ __forceinline__ void split2h(float a, float b, uint32_t& h, uint32_t& l) {
    __half2 hh = __floats2half2_rn(a, b);
    float ar = a - __low2float(hh), br = b - __high2float(hh);
    h = *(uint32_t*)&hh;
    l = pack_h2(ar, br);
}

// ---------------- one-shot convert: x + all weights -> fp16 hi ----------------
__global__ void __launch_bounds__(256) split_all(
    const float* __restrict__ x,  const float* __restrict__ wqd,
    const float* __restrict__ wkd, const float* __restrict__ wqu,
    const float* __restrict__ wku, const float* __restrict__ wo)
{
    int b = blockIdx.x;
    const float* src; fp16* dh; int i;
    if (b < 4096)       { src = x;   dh = g_xh;    i = b * 256; }
    else if (b < 7168)  { src = wqd; dh = g_wqdh;  i = (b - 4096) * 256; }
    else if (b < 8320)  { src = wkd; dh = g_wkvdh; i = (b - 7168) * 256; }
    else if (b < 12928) { src = wqu; dh = g_wquh;  i = (b - 8320) * 256; }
    else if (b < 14976) { src = wku; dh = g_wkvuh; i = (b - 12928) * 256; }
    else                { src = wo;  dh = g_woh;   i = (b - 14976) * 256; }
    i += threadIdx.x;
    float4 v = ((const float4*)src)[i];
    ((uint2*)dh)[i] = make_uint2(pack_h2(v.x, v.y), pack_h2(v.z, v.w));
}

// ---------------- fp16 1-pass NT GEMM: CTA 128x256, 16 warps, warp tile 32x64 ----------------
// 3-stage cp.async pipeline, ONE __syncthreads per k-iteration.
// C = Ah Bh^T + bias.
// mode 0: f32 C; mode 1: q_up rope+round->g_qfh; mode 2: kv_up split K / round V;
// mode 3: kv_down f32 C + k_pe rope/broadcast split->kf
#define GM_SMEM (3*24576)   // 3 stages x (A 8KB, B 16KB)

__global__ void __launch_bounds__(512, 1) gemm_mma2(
    const fp16* __restrict__ Ah0, const fp16* __restrict__ Bh0,
    const float* __restrict__ bias0, float* __restrict__ C0, int N0, int K0, int mode0, int NX0,
    const fp16* __restrict__ Ah1, const fp16* __restrict__ Bh1,
    const float* __restrict__ bias1, float* __restrict__ C1, int N1, int K1, int mode1,
    const float* __restrict__ fc, const float* __restrict__ fs)
{
    extern __shared__ __align__(1024) char sm[];
    const uint32_t smb = smem_u32(sm);

    const fp16 *Ah, *Bh;
    const float* bias;
    float* C;
    int N, K, mode, bx = blockIdx.x;
    if (bx < NX0) {
        Ah = Ah0; Bh = Bh0; bias = bias0; C = C0; N = N0; K = K0; mode = mode0;
    } else {
        bx -= NX0;
        Ah = Ah1; Bh = Bh1; bias = bias1; C = C1; N = N1; K = K1; mode = mode1;
    }

    const int tid = threadIdx.x;
    const int lane = tid & 31;
    const int wid = tid >> 5;          // 0..15
    const int warp_m = wid & 3;        // 4 groups of 32 rows
    const int warp_n = wid >> 2;       // 4 groups of 64 cols
    const int brow = blockIdx.y * 128;
    const int bcol = bx * 256;

    uint32_t aoff[2][2], boff[4][2];
#pragma unroll
    for (int mt = 0; mt < 2; mt++)
#pragma unroll
        for (int ks = 0; ks < 2; ks++) {
            int rr = warp_m * 32 + mt * 16 + (lane & 15);
            int cc = ks * 2 + (lane >> 4);
            aoff[mt][ks] = off16(rr, cc) * 16;
        }
#pragma unroll
    for (int g = 0; g < 4; g++)
#pragma unroll
        for (int ks = 0; ks < 2; ks++) {
            int rr = warp_n * 64 + g * 16 + (lane & 15);
            int cc = ks * 2 + (lane >> 4);
            boff[g][ks] = off16(rr, cc) * 16;
        }

    float acc[2][8][4];
#pragma unroll
    for (int i = 0; i < 2; i++)
#pragma unroll
        for (int j = 0; j < 8; j++)
#pragma unroll
            for (int k = 0; k < 4; k++) acc[i][j][k] = 0.f;

    const int KT = K >> 5;

    // per-stage loads: A 512 chunks (1/thread), B 1024 chunks (2/thread)
    auto load_stage = [&](int s, int k0) {
        uint32_t base = smb + s * 24576;
        {
            int r = tid >> 2, c = tid & 3;
            size_t ga = (size_t)(brow + r) * K + k0 + c * 8;
            CP_ASYNC16(base + off16(r, c) * 16, Ah + ga, 16);
        }
#pragma unroll
        for (int it = 0; it < 2; it++) {
            int id = tid + it * 512;          // 0..1023
            int r = id >> 2, c = id & 3;
            int gr = bcol + r;
            int ok = (gr < N) ? 16 : 0;
            size_t gb = (size_t)(ok ? gr : 0) * K + k0 + c * 8;
            CP_ASYNC16(base + 8192 + off16(r, c) * 16, Bh + gb, ok);
        }
        CP_COMMIT();
    };

    load_stage(0, 0);
    load_stage(1, 32);

    uint32_t af[2][2][4];

    int buf = 0;
    for (int kt = 0; kt < KT; kt++) {
        if (kt + 1 < KT) CP_WAIT(1); else CP_WAIT(0);
        __syncthreads();
        if (kt + 2 < KT) {
            int nb = buf + 2; if (nb >= 3) nb -= 3;
            load_stage(nb, (kt + 2) * 32);
        }

        uint32_t st = smb + buf * 24576;

#pragma unroll
        for (int mt = 0; mt < 2; mt++)
#pragma unroll
            for (int ks = 0; ks < 2; ks++)
                ldsm4(st + aoff[mt][ks], af[mt][ks]);

#pragma unroll
        for (int g = 0; g < 4; g++) {
            uint32_t bf0[4], bf1[4];
            ldsm4(st + 8192 + boff[g][0], bf0);
            ldsm4(st + 8192 + boff[g][1], bf1);
#pragma unroll
            for (int mt = 0; mt < 2; mt++)
#pragma unroll
                for (int hf = 0; hf < 2; hf++) {
                    int n8 = g * 2 + hf;
                    MMAH(acc[mt][n8], af[mt][0], bf0[hf], bf0[hf + 2]);
                    MMAH(acc[mt][n8], af[mt][1], bf1[hf], bf1[hf + 2]);
                }
        }

        buf++; if (buf >= 3) buf = 0;
    }

    // ---- fused epilogues ----
#pragma unroll
    for (int mt = 0; mt < 2; mt++) {
        int row = brow + warp_m * 32 + mt * 16 + (lane >> 2);
#pragma unroll
        for (int n8 = 0; n8 < 8; n8++) {
            int col = bcol + warp_n * 64 + n8 * 8 + (lane & 3) * 2;
            if (col >= N) continue;
            float b0 = bias[col], b1 = bias[col + 1];
            float v00 = acc[mt][n8][0] + b0, v01 = acc[mt][n8][1] + b1;
            float v10 = acc[mt][n8][2] + b0, v11 = acc[mt][n8][3] + b1;

            if (mode == 0) {
                *(float2*)(C + (size_t)row * N + col) = make_float2(v00, v01);
                *(float2*)(C + (size_t)(row + 8) * N + col) = make_float2(v10, v11);
            } else if (mode == 1) {
                int h = col / QK_D, d = col - h * QK_D;
                if (d >= NOPE_D) {
                    int p0 = (d - NOPE_D) >> 1;
                    float c0 = fc[row * 32 + p0], s0 = fs[row * 32 + p0];
                    float t0 = v00 * c0 - v01 * s0;
                    v01 = v00 * s0 + v01 * c0; v00 = t0;
                    float c1 = fc[(row + 8) * 32 + p0], s1 = fs[(row + 8) * 32 + p0];
                    float t1 = v10 * c1 - v11 * s1;
                    v11 = v10 * s1 + v11 * c1; v10 = t1;
                }
                size_t o0 = ((size_t)row * H_N + h) * QK_D + d;
                size_t o1 = ((size_t)(row + 8) * H_N + h) * QK_D + d;
                *(uint32_t*)(g_qfh + o0) = pack_h2(v00, v01);
                *(uint32_t*)(g_qfh + o1) = pack_h2(v10, v11);
            } else if (mode == 2) {
                int h = col >> 8, dd = col & 255;
                if (dd < NOPE_D) {
                    uint32_t hh, ll;
                    size_t o0 = ((size_t)row * H_N + h) * QK_D + dd;
                    size_t o1 = ((size_t)(row + 8) * H_N + h) * QK_D + dd;
                    split2h(v00, v01, hh, ll);
                    *(uint32_t*)(g_kfh + o0) = hh; *(uint32_t*)(g_kfl + o0) = ll;
                    split2h(v10, v11, hh, ll);
                    *(uint32_t*)(g_kfh + o1) = hh; *(uint32_t*)(g_kfl + o1) = ll;
                } else {
                    size_t o0 = ((size_t)row * H_N + h) * VH_D + (dd - NOPE_D);
                    size_t o1 = ((size_t)(row + 8) * H_N + h) * VH_D + (dd - NOPE_D);
                    *(uint32_t*)(g_vfh + o0) = pack_h2(v00, v01);
                    *(uint32_t*)(g_vfh + o1) = pack_h2(v10, v11);
                }
            } else {  // mode 3: kv_down
                *(float2*)(C + (size_t)row * N + col) = make_float2(v00, v01);
                *(float2*)(C + (size_t)(row + 8) * N + col) = make_float2(v10, v11);
                if (col >= KVLORA) {
                    int d = col - KVLORA;
                    int p0 = d >> 1;
                    float c0 = fc[row * 32 + p0], s0 = fs[row * 32 + p0];
                    float r00 = v00 * c0 - v01 * s0;
                    float r01 = v00 * s0 + v01 * c0;
                    float c1 = fc[(row + 8) * 32 + p0], s1 = fs[(row + 8) * 32 + p0];
                    float r10 = v10 * c1 - v11 * s1;
                    float r11 = v10 * s1 + v11 * c1;
                    uint32_t h0p, l0p, h1p, l1p;
                    split2h(r00, r01, h0p, l0p);
                    split2h(r10, r11, h1p, l1p);
#pragma unroll
                    for (int hh = 0; hh < H_N; hh++) {
                        size_t o0 = ((size_t)row * H_N + hh) * QK_D + NOPE_D + d;
                        size_t o1 = ((size_t)(row + 8) * H_N + hh) * QK_D + NOPE_D + d;
                        *(uint32_t*)(g_kfh + o0) = h0p; *(uint32_t*)(g_kfl + o0) = l0p;
                        *(uint32_t*)(g_kfh + o1) = h1p; *(uint32_t*)(g_kfl + o1) = l1p;
                    }
                }
            }
        }
    }
}

// ---------------- fused dual RMSNorm -> fp16 (hi only) ----------------
__global__ void __launch_bounds__(256) mla_rmsnorm2(
    const float* __restrict__ qnw, const float* __restrict__ kvnw)
{
    int row = blockIdx.x;
    const float* x; const float* w; fp16* y; int L;
    if (row < S_LEN) {
        x = g_qdown + (size_t)row * QLORA; w = qnw;
        y = g_qdnh + (size_t)row * QLORA; L = QLORA;
    } else {
        row -= S_LEN;
        x = g_kv + (size_t)row * KVD; w = kvnw;
        y = g_kvnh + (size_t)row * KVLORA; L = KVLORA;
    }
    float ss = 0.f;
    for (int c = threadIdx.x; c < L; c += blockDim.x) {
        float v = x[c];
        ss = fmaf(v, v, ss);
    }
#pragma unroll
    for (int o = 16; o; o >>= 1) ss += __shfl_xor_sync(0xffffffffu, ss, o);
    __shared__ float red[8];
    __shared__ float s_inv;
    if ((threadIdx.x & 31) == 0) red[threadIdx.x >> 5] = ss;
    __syncthreads();
    if (threadIdx.x == 0) {
        float t = 0.f;
#pragma unroll
        for (int i = 0; i < 8; i++) t += red[i];
        s_inv = rsqrtf(t / (float)L + 1e-6f);
    }
    __syncthreads();
    float inv = s_inv;
    for (int c = threadIdx.x; c < L / 2; c += blockDim.x) {
        float2 v = ((const float2*)x)[c];
        float2 ww = ((const float2*)w)[c];
        *(uint32_t*)(y + c * 2) = pack_h2(ww.x * (v.x * inv), ww.y * (v.y * inv));
    }
}

// ---------------- fp16 flash attention (causal, split-KV; K hi+lo, V hi only) ----------------
// 3-stage K/V pipeline, one __syncthreads per key-block iteration.
#define FQ 128
#define FK 32
#define QSTRB 400
#define VSTRB 272
#define SQ  0
#define SK  51200            // 3 stages x (Kh 12800 + Kl 12800)
#define KSTAGE 25600
#define SV  128000           // 3 stages x (Vh 8704)
#define VSTAGE 8704
#define FLASH_SMEM 154112

__global__ void __launch_bounds__(256, 1) mla_flash_mma(
    const fp16* __restrict__ Qh,
    const fp16* __restrict__ Kh, const fp16* __restrict__ Kl,
    const fp16* __restrict__ Vh,
    fp16* __restrict__ O)
{
    extern __shared__ __align__(1024) char fsmem[];
    const uint32_t smb = smem_u32(fsmem);

    const int h = blockIdx.y;
    const int qb = c_qb[blockIdx.x];
    const int part = c_pt[blockIdx.x];
    const int qbase = qb * FQ;
    const int tid = threadIdx.x;
    const int lane = tid & 31;
    const int wid = tid >> 5;
    const int row_min = qbase + wid * 16;

    const int u_total = 4 * (qb + 1);
    const int u_cnt = (part < 0) ? u_total : (u_total >> 1);
    const int u0 = (part < 0) ? 0 : part * u_cnt;

    for (int i = tid; i < FQ * 24; i += 256) {
        int r = i / 24, c = i % 24;
        size_t go = ((size_t)(qbase + r) * H_N + h) * QK_D + c * 8;
        CP_ASYNC16(smb + SQ + (uint32_t)(r * QSTRB + c * 16), Qh + go, 16);
    }
    CP_COMMIT();

    auto load_kv = [&](int s, int kbase) {
        uint32_t kbp = smb + SK + s * KSTAGE;
        uint32_t vbp = smb + SV + s * VSTAGE;
#pragma unroll
        for (int it = 0; it < 3; it++) {
            int i = tid + it * 256;
            int r = i / 24, c = i % 24;
            size_t go = ((size_t)(kbase + r) * H_N + h) * QK_D + c * 8;
            uint32_t so = (uint32_t)(r * QSTRB + c * 16);
            CP_ASYNC16(kbp + so, Kh + go, 16);
            CP_ASYNC16(kbp + 12800 + so, Kl + go, 16);
        }
        {
            int i = tid;
            int r = i >> 4, c = i & 15;
            size_t go = ((size_t)(kbase + r) * H_N + h) * VH_D + c * 8;
            CP_ASYNC16(vbp + (uint32_t)(r * VSTRB + c * 16), Vh + go, 16);
            i = tid + 256;
            r = i >> 4; c = i & 15;
            go = ((size_t)(kbase + r) * H_N + h) * VH_D + c * 8;
            CP_ASYNC16(vbp + (uint32_t)(r * VSTRB + c * 16), Vh + go, 16);
        }
        CP_COMMIT();
    };

    const uint32_t qfb = smb + SQ + (uint32_t)((wid * 16 + (lane & 15)) * QSTRB + (lane >> 4) * 16);
    const uint32_t kfrel = (uint32_t)((lane & 15) * QSTRB + (lane >> 4) * 16);
    const uint32_t vfrel = (uint32_t)((lane & 15) * VSTRB + (lane >> 4) * 16);

    float o[16][4];
#pragma unroll
    for (int g = 0; g < 16; g++)
#pragma unroll
        for (int j = 0; j < 4; j++) o[g][j] = 0.f;
    float m0 = -1e30f, m1 = -1e30f, l0 = 0.f, l1 = 0.f;
    const float scale = 0.07216878364870322f;

    load_kv(0, u0 * FK);
    if (u_cnt > 1) load_kv(1, (u0 + 1) * FK);

    int buf = 0;
    for (int kb = 0; kb < u_cnt; kb++) {
        const int kbase = (u0 + kb) * FK;
        if (kb + 1 < u_cnt) CP_WAIT(1); else CP_WAIT(0);
        __syncthreads();
        if (kb + 2 < u_cnt) {
            int nb = buf + 2; if (nb >= 3) nb -= 3;
            load_kv(nb, (u0 + kb + 2) * FK);
        }

        if (kbase <= row_min) {
            uint32_t kst = smb + SK + buf * KSTAGE;
            uint32_t vst = smb + SV + buf * VSTAGE;

            float c[4][4];
#pragma unroll
            for (int g = 0; g < 4; g++)
#pragma unroll
                for (int j = 0; j < 4; j++) c[g][j] = 0.f;

#pragma unroll
            for (int ks = 0; ks < 12; ks++) {
                uint32_t ah[4];
                ldsm4(qfb + ks * 32, ah);
#pragma unroll
                for (int gg = 0; gg < 2; gg++) {
                    uint32_t bh[4], bl[4];
                    ldsm4(kst + kfrel + gg * (16 * QSTRB) + ks * 32, bh);
                    ldsm4(kst + 12800 + kfrel + gg * (16 * QSTRB) + ks * 32, bl);
                    MMAH(c[2 * gg],     ah, bh[0], bh[2]);
                    MMAH(c[2 * gg + 1], ah, bh[1], bh[3]);
                    MMAH(c[2 * gg],     ah, bl[0], bl[2]);
                    MMAH(c[2 * gg + 1], ah, bl[1], bl[3]);
                }
            }

            const int row0 = row_min + (lane >> 2);
            const bool needmask = (kbase + FK - 1 > row_min);
#pragma unroll
            for (int g = 0; g < 4; g++) {
                int col = kbase + g * 8 + (lane & 3) * 2;
#pragma unroll
                for (int j = 0; j < 4; j++) {
                    float v = c[g][j] * scale;
                    if (needmask) {
                        int cc = col + (j & 1);
                        int rr = row0 + ((j >> 1) << 3);
                        if (cc > rr) v = -1e30f;
                    }
                    c[g][j] = v;
                }
            }

            float mx0 = -1e30f, mx1 = -1e30f;
#pragma unroll
            for (int g = 0; g < 4; g++) {
                mx0 = fmaxf(mx0, fmaxf(c[g][0], c[g][1]));
                mx1 = fmaxf(mx1, fmaxf(c[g][2], c[g][3]));
            }
#pragma unroll
            for (int off = 1; off < 4; off <<= 1) {
                mx0 = fmaxf(mx0, __shfl_xor_sync(0xffffffffu, mx0, off));
                mx1 = fmaxf(mx1, __shfl_xor_sync(0xffffffffu, mx1, off));
            }
            float mn0 = fmaxf(m0, mx0), mn1 = fmaxf(m1, mx1);
            float al0 = __expf(m0 - mn0), al1 = __expf(m1 - mn1);
            float rs0 = 0.f, rs1 = 0.f;
#pragma unroll
            for (int g = 0; g < 4; g++) {
                c[g][0] = __expf(c[g][0] - mn0); rs0 += c[g][0];
                c[g][1] = __expf(c[g][1] - mn0); rs0 += c[g][1];
                c[g][2] = __expf(c[g][2] - mn1); rs1 += c[g][2];
                c[g][3] = __expf(c[g][3] - mn1); rs1 += c[g][3];
            }
#pragma unroll
            for (int off = 1; off < 4; off <<= 1) {
                rs0 += __shfl_xor_sync(0xffffffffu, rs0, off);
                rs1 += __shfl_xor_sync(0xffffffffu, rs1, off);
            }
            l0 = l0 * al0 + rs0; l1 = l1 * al1 + rs1;
            m0 = mn0; m1 = mn1;
#pragma unroll
            for (int g = 0; g < 16; g++) {
                o[g][0] *= al0; o[g][1] *= al0;
                o[g][2] *= al1; o[g][3] *= al1;
            }

            // O += P * Vh  (single pass)
#pragma unroll
            for (int kc = 0; kc < 2; kc++) {
                uint32_t aph[4];
                aph[0] = pack_h2(c[2 * kc][0],     c[2 * kc][1]);
                aph[1] = pack_h2(c[2 * kc][2],     c[2 * kc][3]);
                aph[2] = pack_h2(c[2 * kc + 1][0], c[2 * kc + 1][1]);
                aph[3] = pack_h2(c[2 * kc + 1][2], c[2 * kc + 1][3]);
#pragma unroll
                for (int ng = 0; ng < 8; ng++) {
                    uint32_t vh4[4];
                    ldsm4t(vst + vfrel + kc * (16 * VSTRB) + ng * 32, vh4);
                    MMAH(o[2 * ng],     aph, vh4[0], vh4[1]);
                    MMAH(o[2 * ng + 1], aph, vh4[2], vh4[3]);
                }
            }
        }
        buf++; if (buf >= 3) buf = 0;
    }

    const int rl0 = wid * 16 + (lane >> 2);
    if (part < 0) {
        float inv0 = 1.0f / l0, inv1 = 1.0f / l1;
        int row0 = qbase + rl0;
#pragma unroll
        for (int g = 0; g < 16; g++) {
            int col = h * VH_D + g * 8 + (lane & 3) * 2;
            *(uint32_t*)(O + (size_t)row0 * ATTN_N + col) =
                pack_h2(o[g][0] * inv0, o[g][1] * inv0);
            *(uint32_t*)(O + (size_t)(row0 + 8) * ATTN_N + col) =
                pack_h2(o[g][2] * inv1, o[g][3] * inv1);
        }
    } else {
        const int sb = (h * 8 + (qb - 8)) * 2 + part;
        const size_t ob0 = ((size_t)sb * 128 + rl0) * 128;
        const size_t ob1 = ((size_t)sb * 128 + rl0 + 8) * 128;
#pragma unroll
        for (int g = 0; g < 16; g++) {
            int col = g * 8 + (lane & 3) * 2;
            *(float2*)(g_fo + ob0 + col) = make_float2(o[g][0], o[g][1]);
            *(float2*)(g_fo + ob1 + col) = make_float2(o[g][2], o[g][3]);
        }
        if ((lane & 3) == 0) {
            g_fm[sb * 128 + rl0] = m0;     g_fl[sb * 128 + rl0] = l0;
            g_fm[sb * 128 + rl0 + 8] = m1; g_fl[sb * 128 + rl0 + 8] = l1;
        }
    }
}

// ---------------- flash split-KV merge ----------------
__global__ void __launch_bounds__(256) flash_merge(fp16* __restrict__ O)
{
    int t = threadIdx.x;
    int rl = blockIdx.x * 4 + (t >> 6);
    int h = rl >> 10;
    int rem = rl & 1023;
    int qbs = rem >> 7;
    int row = rem & 127;
    int c = (t & 63) * 2;

    int i0 = ((h * 8 + qbs) * 2 + 0) * 128 + row;
    int i1 = ((h * 8 + qbs) * 2 + 1) * 128 + row;
    float m0 = g_fm[i0], m1 = g_fm[i1];
    float l0 = g_fl[i0], l1 = g_fl[i1];
    float m = fmaxf(m0, m1);
    float w0 = __expf(m0 - m), w1 = __expf(m1 - m);
    float inv = 1.f / (w0 * l0 + w1 * l1);

    float2 a = *(float2*)(g_fo + (size_t)i0 * 128 + c);
    float2 b = *(float2*)(g_fo + (size_t)i1 * 128 + c);
    size_t off = (size_t)((qbs + 8) * 128 + row) * ATTN_N + h * VH_D + c;
    *(uint32_t*)(O + off) = pack_h2((w0 * a.x + w1 * b.x) * inv,
                                    (w0 * a.y + w1 * b.y) * inv);
}

// ---------------- launch ----------------
extern "C" void kernel_launch(void* const* d_in, const int* in_sizes, int n_in,
                              void* d_out, int out_size)
{
    const float* x          = (const float*)d_in[0];
    const float* fcos       = (const float*)d_in[2];
    const float* fsin       = (const float*)d_in[3];
    const float* wq_down_w  = (const float*)d_in[5];
    const float* wq_down_b  = (const float*)d_in[6];
    const float* q_norm_w   = (const float*)d_in[7];
    const float* wq_up_w    = (const float*)d_in[8];
    const float* wq_up_b    = (const float*)d_in[9];
    const float* wkv_down_w = (const float*)d_in[10];
    const float* wkv_down_b = (const float*)d_in[11];
    const float* kv_norm_w  = (const float*)d_in[12];
    const float* wkv_up_w   = (const float*)d_in[13];
    const float* wkv_up_b   = (const float*)d_in[14];
    const float* wo_w       = (const float*)d_in[15];
    const float* wo_b       = (const float*)d_in[16];
    float* out = (float*)d_out;

    float *qdown, *kv;
    fp16 *xh, *qdnh, *kvnh, *attnh, *qfh, *kfh, *kfl, *vfh;
    fp16 *wqdh, *wkvdh, *wquh, *wkvuh, *woh;
    cudaGetSymbolAddress((void**)&qdown, g_qdown);
    cudaGetSymbolAddress((void**)&kv,    g_kv);
    cudaGetSymbolAddress((void**)&xh, g_xh);
    cudaGetSymbolAddress((void**)&qdnh, g_qdnh);
    cudaGetSymbolAddress((void**)&kvnh, g_kvnh);
    cudaGetSymbolAddress((void**)&attnh, g_attnh);
    cudaGetSymbolAddress((void**)&qfh, g_qfh);
    cudaGetSymbolAddress((void**)&kfh, g_kfh);   cudaGetSymbolAddress((void**)&kfl, g_kfl);
    cudaGetSymbolAddress((void**)&vfh, g_vfh);
    cudaGetSymbolAddress((void**)&wqdh, g_wqdh);
    cudaGetSymbolAddress((void**)&wkvdh, g_wkvdh);
    cudaGetSymbolAddress((void**)&wquh, g_wquh);
    cudaGetSymbolAddress((void**)&wkvuh, g_wkvuh);
    cudaGetSymbolAddress((void**)&woh, g_woh);

    cudaFuncSetAttribute(gemm_mma2, cudaFuncAttributeMaxDynamicSharedMemorySize, GM_SMEM);
    cudaFuncSetAttribute(mla_flash_mma, cudaFuncAttributeMaxDynamicSharedMemorySize, FLASH_SMEM);

    // one-shot convert: x + all 5 weights -> fp16 hi
    split_all<<<19072, 256>>>(x, wq_down_w, wkv_down_w, wq_up_w, wkv_up_w, wo_w);

    // batched down projections: q_down (6 col tiles, mode 0) + kv_down (3 tiles, mode 3)
    gemm_mma2<<<dim3(6 + 3, S_LEN / 128), 512, GM_SMEM>>>(
        xh, wqdh, wq_down_b, qdown, QLORA, D_DIM, 0, 6,
        xh, wkvdh, wkv_down_b, kv, KVD, D_DIM, 3,
        fcos, fsin);

    // fused dual rmsnorm
    mla_rmsnorm2<<<2 * S_LEN, 256>>>(q_norm_w, kv_norm_w);

    // batched up projections: q_up (12 tiles, mode 1) + kv_up (16 tiles, mode 2)
    gemm_mma2<<<dim3(12 + 16, S_LEN / 128), 512, GM_SMEM>>>(
        qdnh, wquh, wq_up_b, qdown, QUP_N, QLORA, 1, 12,
        kvnh, wkvuh, wkv_up_b, qdown, KVUP_N, KVLORA, 2,
        fcos, fsin);

    // flash attention with split-KV (384 CTAs, size-descending, 3-stage pipeline)
    mla_flash_mma<<<dim3(24, H_N), 256, FLASH_SMEM>>>(
        qfh, kfh, kfl, vfh, attnh);
    flash_merge<<<4096, 256>>>(attnh);

    // output projection (8 col tiles, mode 0; second slot inert)
    gemm_mma2<<<dim3(8, S_LEN / 128), 512, GM_SMEM>>>(
        attnh, woh, wo_b, out, D_DIM, ATTN_N, 0, 8,
        attnh, woh, wo_b, out, D_DIM, ATTN_N, 0,
        fcos, fsin);
}